// round 1
// baseline (speedup 1.0000x reference)
#include <cuda_runtime.h>
#include <cstdint>
#include <math.h>

// ---------------------------------------------------------------------------
// DecLayer: B=4, N=2048, K=48, H=IN=128
//   stage1: per-edge 3-layer MLP (256->128->128->128), masked sum over K,
//           residual + LN1 -> g_hV1
//   stage2: FFN 128->512->128, residual + LN2, * mask_V -> d_out[hV region]
//   stage3: per-edge 3-layer MLP (384->128->128->128) with gather,
//           residual + LN3 -> d_out[hE region]
// GEMMs run on tf32 mma.sync.m16n8k8 with fp32 accumulation.
// ---------------------------------------------------------------------------

#define EPSLN 1e-5f

static constexpr int Bc = 4, Nc = 2048, Kc = 48, Hc = 128;
static constexpr int BN = Bc * Nc;              // 8192 nodes
static constexpr long ETOT = (long)BN * Kc;     // 393216 edges
static constexpr long VOUT = (long)BN * Hc;     // 1048576 floats

__device__ float g_hV1[BN * Hc];                // scratch: h_V after LN1 (4 MB)

static __device__ __forceinline__ uint32_t f2tf(float f) {
    uint32_t u;
    asm("cvt.rna.tf32.f32 %0, %1;" : "=r"(u) : "f"(f));
    return u;
}

static __device__ __forceinline__ void mma8(float* d, const uint32_t* a, const uint32_t* b) {
    asm volatile(
        "mma.sync.aligned.m16n8k8.row.col.f32.tf32.tf32.f32 "
        "{%0,%1,%2,%3},{%4,%5,%6,%7},{%8,%9},{%0,%1,%2,%3};"
        : "+f"(d[0]), "+f"(d[1]), "+f"(d[2]), "+f"(d[3])
        : "r"(a[0]), "r"(a[1]), "r"(a[2]), "r"(a[3]), "r"(b[0]), "r"(b[1]));
}

static __device__ __forceinline__ float gelu_t(float x) {
    float x3 = x * x * x;
    return 0.5f * x * (1.0f + tanhf(0.7978845608028654f * (x + 0.044715f * x3)));
}

// ======================= Stage 1: node message + LN1 =======================
// block: 4 nodes = 192 edge rows. 256 threads = 8 warps, warp grid 4x2,
// warp tile 48x64 (mi=3 x16, ni=8 x8).
static constexpr int SM1 = 192 * 132 * 4      // Hs (activation tile, tf32/float)
                         + 192 * 36 * 4       // Xs (input k-chunk)
                         + 32 * 136 * 4       // Ws (weight k-chunk)
                         + (640 + 192 + 512) * 4; // biases+ln, mask rows, P

__global__ __launch_bounds__(256, 1) void k_stage1(
    const float* __restrict__ hV, const float* __restrict__ hE,
    const float* __restrict__ mA,
    const float* __restrict__ W1, const float* __restrict__ b1,
    const float* __restrict__ W2, const float* __restrict__ b2,
    const float* __restrict__ W3, const float* __restrict__ b3,
    const float* __restrict__ lng, const float* __restrict__ lnb)
{
    extern __shared__ unsigned char smraw[];
    uint32_t (*Hs)[132] = reinterpret_cast<uint32_t(*)[132]>(smraw);
    uint32_t (*Xs)[36]  = reinterpret_cast<uint32_t(*)[36]>(smraw + 192 * 132 * 4);
    uint32_t (*Ws)[136] = reinterpret_cast<uint32_t(*)[136]>(smraw + 192 * 132 * 4 + 192 * 36 * 4);
    float* sb    = reinterpret_cast<float*>(smraw + 192 * 132 * 4 + 192 * 36 * 4 + 32 * 136 * 4);
    float* smask = sb + 640;
    float* P     = smask + 192;

    const int tid = threadIdx.x, warp = tid >> 5, lane = tid & 31;
    const int g = lane >> 2, tg = lane & 3;
    const int wm = warp >> 1, wn = warp & 1;
    const int node0 = blockIdx.x * 4;
    const long e0 = (long)node0 * Kc;

    for (int i = tid; i < 128; i += 256) {
        sb[i] = b1[i]; sb[128 + i] = b2[i]; sb[256 + i] = b3[i];
        sb[384 + i] = lng[i]; sb[512 + i] = lnb[i];
    }
    for (int i = tid; i < 192; i += 256) smask[i] = mA[e0 + i];

    float acc[3][8][4];
#pragma unroll
    for (int mi = 0; mi < 3; mi++)
#pragma unroll
        for (int ni = 0; ni < 8; ni++)
#pragma unroll
            for (int q = 0; q < 4; q++) acc[mi][ni][q] = 0.f;

    // ---- layer 1: X[192,256] @ W1[256,128]
    for (int kc = 0; kc < 8; kc++) {
        for (int i = tid; i < 192 * 32; i += 256) {
            int r = i >> 5, c = i & 31;
            int col = kc * 32 + c;
            float v = (col < 128)
                    ? hV[(long)(node0 + r / Kc) * Hc + col]
                    : hE[(e0 + r) * Hc + (col - 128)];
            Xs[r][c] = f2tf(v);
        }
        for (int i = tid; i < 32 * 128; i += 256) {
            int r = i >> 7, c = i & 127;
            Ws[r][c] = f2tf(W1[(kc * 32 + r) * 128 + c]);
        }
        __syncthreads();
#pragma unroll
        for (int ks = 0; ks < 4; ks++) {
            const int kk = ks * 8;
            uint32_t a[3][4], bf[8][2];
#pragma unroll
            for (int mi = 0; mi < 3; mi++) {
                int r = wm * 48 + mi * 16;
                a[mi][0] = Xs[r + g][kk + tg];     a[mi][1] = Xs[r + g + 8][kk + tg];
                a[mi][2] = Xs[r + g][kk + tg + 4]; a[mi][3] = Xs[r + g + 8][kk + tg + 4];
            }
#pragma unroll
            for (int ni = 0; ni < 8; ni++) {
                int c = wn * 64 + ni * 8 + g;
                bf[ni][0] = Ws[kk + tg][c]; bf[ni][1] = Ws[kk + tg + 4][c];
            }
#pragma unroll
            for (int mi = 0; mi < 3; mi++)
#pragma unroll
                for (int ni = 0; ni < 8; ni++) mma8(acc[mi][ni], a[mi], bf[ni]);
        }
        __syncthreads();
    }
    // epilogue 1: gelu -> Hs (tf32)
#pragma unroll
    for (int mi = 0; mi < 3; mi++) {
        int r0 = wm * 48 + mi * 16 + g;
#pragma unroll
        for (int ni = 0; ni < 8; ni++) {
            int c0 = wn * 64 + ni * 8 + 2 * tg;
            Hs[r0][c0]       = f2tf(gelu_t(acc[mi][ni][0] + sb[c0]));
            Hs[r0][c0 + 1]   = f2tf(gelu_t(acc[mi][ni][1] + sb[c0 + 1]));
            Hs[r0 + 8][c0]   = f2tf(gelu_t(acc[mi][ni][2] + sb[c0]));
            Hs[r0 + 8][c0 + 1] = f2tf(gelu_t(acc[mi][ni][3] + sb[c0 + 1]));
        }
    }

    // ---- layers 2 and 3 (in-place on Hs)
    for (int layer = 1; layer < 3; layer++) {
        const float* Wl = (layer == 1) ? W2 : W3;
#pragma unroll
        for (int mi = 0; mi < 3; mi++)
#pragma unroll
            for (int ni = 0; ni < 8; ni++)
#pragma unroll
                for (int q = 0; q < 4; q++) acc[mi][ni][q] = 0.f;
        for (int kc = 0; kc < 4; kc++) {
            for (int i = tid; i < 32 * 128; i += 256) {
                int r = i >> 7, c = i & 127;
                Ws[r][c] = f2tf(Wl[(kc * 32 + r) * 128 + c]);
            }
            __syncthreads();
#pragma unroll
            for (int ks = 0; ks < 4; ks++) {
                const int kk = kc * 32 + ks * 8;
                const int kw = ks * 8;
                uint32_t a[3][4], bf[8][2];
#pragma unroll
                for (int mi = 0; mi < 3; mi++) {
                    int r = wm * 48 + mi * 16;
                    a[mi][0] = Hs[r + g][kk + tg];     a[mi][1] = Hs[r + g + 8][kk + tg];
                    a[mi][2] = Hs[r + g][kk + tg + 4]; a[mi][3] = Hs[r + g + 8][kk + tg + 4];
                }
#pragma unroll
                for (int ni = 0; ni < 8; ni++) {
                    int c = wn * 64 + ni * 8 + g;
                    bf[ni][0] = Ws[kw + tg][c]; bf[ni][1] = Ws[kw + tg + 4][c];
                }
#pragma unroll
                for (int mi = 0; mi < 3; mi++)
#pragma unroll
                    for (int ni = 0; ni < 8; ni++) mma8(acc[mi][ni], a[mi], bf[ni]);
            }
            __syncthreads();
        }
        if (layer == 1) {
#pragma unroll
            for (int mi = 0; mi < 3; mi++) {
                int r0 = wm * 48 + mi * 16 + g;
#pragma unroll
                for (int ni = 0; ni < 8; ni++) {
                    int c0 = wn * 64 + ni * 8 + 2 * tg;
                    Hs[r0][c0]       = f2tf(gelu_t(acc[mi][ni][0] + sb[128 + c0]));
                    Hs[r0][c0 + 1]   = f2tf(gelu_t(acc[mi][ni][1] + sb[128 + c0 + 1]));
                    Hs[r0 + 8][c0]   = f2tf(gelu_t(acc[mi][ni][2] + sb[128 + c0]));
                    Hs[r0 + 8][c0 + 1] = f2tf(gelu_t(acc[mi][ni][3] + sb[128 + c0 + 1]));
                }
            }
        } else {
            // final: (acc + b3) * mask_attend[row]  (store as raw float)
#pragma unroll
            for (int mi = 0; mi < 3; mi++) {
                int r0 = wm * 48 + mi * 16 + g;
                float m0 = smask[r0], m1 = smask[r0 + 8];
#pragma unroll
                for (int ni = 0; ni < 8; ni++) {
                    int c0 = wn * 64 + ni * 8 + 2 * tg;
                    Hs[r0][c0]       = __float_as_uint((acc[mi][ni][0] + sb[256 + c0]) * m0);
                    Hs[r0][c0 + 1]   = __float_as_uint((acc[mi][ni][1] + sb[256 + c0 + 1]) * m0);
                    Hs[r0 + 8][c0]   = __float_as_uint((acc[mi][ni][2] + sb[256 + c0]) * m1);
                    Hs[r0 + 8][c0 + 1] = __float_as_uint((acc[mi][ni][3] + sb[256 + c0 + 1]) * m1);
                }
            }
        }
        __syncthreads();
    }

    // sum over K=48, residual, LN1
    for (int t = tid; t < 512; t += 256) {
        int nn = t >> 7, c = t & 127;
        float s = 0.f;
#pragma unroll 8
        for (int j = 0; j < 48; j++) s += __uint_as_float(Hs[nn * 48 + j][c]);
        P[nn * 128 + c] = hV[(long)(node0 + nn) * Hc + c] + s * (1.0f / 30.0f);
    }
    __syncthreads();
    if (warp < 4) {
        int nn = warp;
        float x[4], s = 0.f, s2 = 0.f;
#pragma unroll
        for (int q = 0; q < 4; q++) {
            x[q] = P[nn * 128 + lane + 32 * q];
            s += x[q]; s2 += x[q] * x[q];
        }
#pragma unroll
        for (int off = 16; off; off >>= 1) {
            s  += __shfl_xor_sync(0xffffffffu, s,  off);
            s2 += __shfl_xor_sync(0xffffffffu, s2, off);
        }
        float mu  = s * (1.0f / 128.0f);
        float var = s2 * (1.0f / 128.0f) - mu * mu;
        float inv = rsqrtf(var + EPSLN);
#pragma unroll
        for (int q = 0; q < 4; q++) {
            int c = lane + 32 * q;
            g_hV1[(long)(node0 + nn) * Hc + c] = (x[q] - mu) * inv * sb[384 + c] + sb[512 + c];
        }
    }
}

// ======================= Stage 2: FFN + LN2 + mask_V =======================
// block: 32 nodes, 256 threads. fp32 FFMA with transposed smem tiles.
static constexpr int SM2 = (128 * 36 + 512 * 36 + 32 * 128 + 896) * 4;

__global__ __launch_bounds__(256, 1) void k_stage2(
    const float* __restrict__ maskV,
    const float* __restrict__ Win,  const float* __restrict__ bin,
    const float* __restrict__ Wout, const float* __restrict__ bout,
    const float* __restrict__ lng,  const float* __restrict__ lnb,
    float* __restrict__ outV)
{
    extern __shared__ unsigned char smraw[];
    float (*HT)[36] = reinterpret_cast<float(*)[36]>(smraw);                 // [k][node]
    float (*TT)[36] = reinterpret_cast<float(*)[36]>(smraw + 128 * 36 * 4);  // [hidden][node]
    float* P  = reinterpret_cast<float*>(smraw + (128 + 512) * 36 * 4);
    float* sb = P + 32 * 128;

    const int tid = threadIdx.x, warp = tid >> 5, lane = tid & 31;
    const int node0 = blockIdx.x * 32;

    for (int i = tid; i < 512; i += 256) sb[i] = bin[i];
    for (int i = tid; i < 128; i += 256) {
        sb[512 + i] = bout[i]; sb[640 + i] = lng[i]; sb[768 + i] = lnb[i];
    }
    for (int i = tid; i < 32 * 128; i += 256) {
        int m = i >> 7, k = i & 127;
        HT[k][m] = g_hV1[(long)(node0 + m) * Hc + k];
    }
    __syncthreads();

    // layer 1: each thread owns hidden cols j0=tid, j1=tid+256 across 32 nodes
    float a0[32], a1[32];
#pragma unroll
    for (int m = 0; m < 32; m++) { a0[m] = 0.f; a1[m] = 0.f; }
    const int j0 = tid, j1 = tid + 256;
    for (int k = 0; k < 128; k++) {
        float w0 = __ldg(&Win[k * 512 + j0]);
        float w1 = __ldg(&Win[k * 512 + j1]);
        const float4* hp = reinterpret_cast<const float4*>(&HT[k][0]);
#pragma unroll
        for (int q = 0; q < 8; q++) {
            float4 h = hp[q];
            a0[4 * q + 0] += h.x * w0; a0[4 * q + 1] += h.y * w0;
            a0[4 * q + 2] += h.z * w0; a0[4 * q + 3] += h.w * w0;
            a1[4 * q + 0] += h.x * w1; a1[4 * q + 1] += h.y * w1;
            a1[4 * q + 2] += h.z * w1; a1[4 * q + 3] += h.w * w1;
        }
    }
    float bj0 = sb[j0], bj1 = sb[j1];
#pragma unroll
    for (int q = 0; q < 8; q++) {
        float4 v0, v1;
        v0.x = gelu_t(a0[4 * q + 0] + bj0); v0.y = gelu_t(a0[4 * q + 1] + bj0);
        v0.z = gelu_t(a0[4 * q + 2] + bj0); v0.w = gelu_t(a0[4 * q + 3] + bj0);
        v1.x = gelu_t(a1[4 * q + 0] + bj1); v1.y = gelu_t(a1[4 * q + 1] + bj1);
        v1.z = gelu_t(a1[4 * q + 2] + bj1); v1.w = gelu_t(a1[4 * q + 3] + bj1);
        *reinterpret_cast<float4*>(&TT[j0][4 * q]) = v0;
        *reinterpret_cast<float4*>(&TT[j1][4 * q]) = v1;
    }
    __syncthreads();

    // layer 2: thread (grp, col) owns 16 nodes at output col
    const int grp = tid >> 7, col = tid & 127;
    float c16[16];
#pragma unroll
    for (int m = 0; m < 16; m++) c16[m] = 0.f;
    for (int k = 0; k < 512; k++) {
        float w = __ldg(&Wout[k * 128 + col]);
        const float4* tp = reinterpret_cast<const float4*>(&TT[k][grp * 16]);
#pragma unroll
        for (int q = 0; q < 4; q++) {
            float4 t = tp[q];
            c16[4 * q + 0] += t.x * w; c16[4 * q + 1] += t.y * w;
            c16[4 * q + 2] += t.z * w; c16[4 * q + 3] += t.w * w;
        }
    }
#pragma unroll
    for (int m = 0; m < 16; m++) {
        int node = grp * 16 + m;
        P[node * 128 + col] = HT[col][node] + c16[m] + sb[512 + col];
    }
    __syncthreads();

    // LN2 + mask_V: warp handles 4 nodes
    for (int q4 = 0; q4 < 4; q4++) {
        int node = warp * 4 + q4;
        float x[4], s = 0.f, s2 = 0.f;
#pragma unroll
        for (int q = 0; q < 4; q++) {
            x[q] = P[node * 128 + lane + 32 * q];
            s += x[q]; s2 += x[q] * x[q];
        }
#pragma unroll
        for (int off = 16; off; off >>= 1) {
            s  += __shfl_xor_sync(0xffffffffu, s,  off);
            s2 += __shfl_xor_sync(0xffffffffu, s2, off);
        }
        float mu  = s * (1.0f / 128.0f);
        float var = s2 * (1.0f / 128.0f) - mu * mu;
        float inv = rsqrtf(var + EPSLN);
        float mv  = maskV[node0 + node];
#pragma unroll
        for (int q = 0; q < 4; q++) {
            int c = lane + 32 * q;
            outV[(long)(node0 + node) * Hc + c] =
                mv * ((x[q] - mu) * inv * sb[640 + c] + sb[768 + c]);
        }
    }
}

// ======================= Stage 3: edge update + LN3 =======================
// block: 128 edge rows. 8 warps, warp grid 4x2, warp tile 32x64.
static constexpr int SM3 = 128 * 132 * 4 + 128 * 36 * 4 + 32 * 136 * 4
                         + 640 * 4 + 256 * 4;

__global__ __launch_bounds__(256, 1) void k_stage3(
    const float* __restrict__ hV2, const float* __restrict__ hE,
    const int* __restrict__ Eidx,
    const float* __restrict__ W11, const float* __restrict__ b11,
    const float* __restrict__ W12, const float* __restrict__ b12,
    const float* __restrict__ W13, const float* __restrict__ b13,
    const float* __restrict__ lng, const float* __restrict__ lnb,
    float* __restrict__ outE)
{
    extern __shared__ unsigned char smraw[];
    uint32_t (*Hs)[132] = reinterpret_cast<uint32_t(*)[132]>(smraw);
    uint32_t (*Xs)[36]  = reinterpret_cast<uint32_t(*)[36]>(smraw + 128 * 132 * 4);
    uint32_t (*Ws)[136] = reinterpret_cast<uint32_t(*)[136]>(smraw + 128 * 132 * 4 + 128 * 36 * 4);
    float* sb = reinterpret_cast<float*>(smraw + 128 * 132 * 4 + 128 * 36 * 4 + 32 * 136 * 4);
    int* rN = reinterpret_cast<int*>(sb + 640);
    int* rB = rN + 128;

    const int tid = threadIdx.x, warp = tid >> 5, lane = tid & 31;
    const int g = lane >> 2, tg = lane & 3;
    const int wm = warp >> 1, wn = warp & 1;
    const long e0 = (long)blockIdx.x * 128;

    for (int i = tid; i < 128; i += 256) {
        sb[i] = b11[i]; sb[128 + i] = b12[i]; sb[256 + i] = b13[i];
        sb[384 + i] = lng[i]; sb[512 + i] = lnb[i];
    }
    if (tid < 128) {
        long e = e0 + tid;
        int bn = (int)(e / Kc);
        rN[tid] = bn;
        int b = bn >> 11;                       // / 2048
        rB[tid] = (b << 11) + Eidx[e];
    }
    __syncthreads();

    float acc[2][8][4];
#pragma unroll
    for (int mi = 0; mi < 2; mi++)
#pragma unroll
        for (int ni = 0; ni < 8; ni++)
#pragma unroll
            for (int q = 0; q < 4; q++) acc[mi][ni][q] = 0.f;

    // ---- layer 1: X[128,384] @ W11[384,128]
    for (int kc = 0; kc < 12; kc++) {
        for (int i = tid; i < 128 * 32; i += 256) {
            int r = i >> 5, c = i & 31;
            int col = kc * 32 + c;
            float v;
            if (col < 128)       v = hV2[(long)rN[r] * Hc + col];
            else if (col < 256)  v = hE[(e0 + r) * Hc + (col - 128)];
            else                 v = hV2[(long)rB[r] * Hc + (col - 256)];
            Xs[r][c] = f2tf(v);
        }
        for (int i = tid; i < 32 * 128; i += 256) {
            int r = i >> 7, c = i & 127;
            Ws[r][c] = f2tf(W11[(kc * 32 + r) * 128 + c]);
        }
        __syncthreads();
#pragma unroll
        for (int ks = 0; ks < 4; ks++) {
            const int kk = ks * 8;
            uint32_t a[2][4], bf[8][2];
#pragma unroll
            for (int mi = 0; mi < 2; mi++) {
                int r = wm * 32 + mi * 16;
                a[mi][0] = Xs[r + g][kk + tg];     a[mi][1] = Xs[r + g + 8][kk + tg];
                a[mi][2] = Xs[r + g][kk + tg + 4]; a[mi][3] = Xs[r + g + 8][kk + tg + 4];
            }
#pragma unroll
            for (int ni = 0; ni < 8; ni++) {
                int c = wn * 64 + ni * 8 + g;
                bf[ni][0] = Ws[kk + tg][c]; bf[ni][1] = Ws[kk + tg + 4][c];
            }
#pragma unroll
            for (int mi = 0; mi < 2; mi++)
#pragma unroll
                for (int ni = 0; ni < 8; ni++) mma8(acc[mi][ni], a[mi], bf[ni]);
        }
        __syncthreads();
    }
#pragma unroll
    for (int mi = 0; mi < 2; mi++) {
        int r0 = wm * 32 + mi * 16 + g;
#pragma unroll
        for (int ni = 0; ni < 8; ni++) {
            int c0 = wn * 64 + ni * 8 + 2 * tg;
            Hs[r0][c0]       = f2tf(gelu_t(acc[mi][ni][0] + sb[c0]));
            Hs[r0][c0 + 1]   = f2tf(gelu_t(acc[mi][ni][1] + sb[c0 + 1]));
            Hs[r0 + 8][c0]   = f2tf(gelu_t(acc[mi][ni][2] + sb[c0]));
            Hs[r0 + 8][c0 + 1] = f2tf(gelu_t(acc[mi][ni][3] + sb[c0 + 1]));
        }
    }

    // ---- layers 2 and 3
    for (int layer = 1; layer < 3; layer++) {
        const float* Wl = (layer == 1) ? W12 : W13;
#pragma unroll
        for (int mi = 0; mi < 2; mi++)
#pragma unroll
            for (int ni = 0; ni < 8; ni++)
#pragma unroll
                for (int q = 0; q < 4; q++) acc[mi][ni][q] = 0.f;
        for (int kc = 0; kc < 4; kc++) {
            for (int i = tid; i < 32 * 128; i += 256) {
                int r = i >> 7, c = i & 127;
                Ws[r][c] = f2tf(Wl[(kc * 32 + r) * 128 + c]);
            }
            __syncthreads();
#pragma unroll
            for (int ks = 0; ks < 4; ks++) {
                const int kk = kc * 32 + ks * 8;
                const int kw = ks * 8;
                uint32_t a[2][4], bf[8][2];
#pragma unroll
                for (int mi = 0; mi < 2; mi++) {
                    int r = wm * 32 + mi * 16;
                    a[mi][0] = Hs[r + g][kk + tg];     a[mi][1] = Hs[r + g + 8][kk + tg];
                    a[mi][2] = Hs[r + g][kk + tg + 4]; a[mi][3] = Hs[r + g + 8][kk + tg + 4];
                }
#pragma unroll
                for (int ni = 0; ni < 8; ni++) {
                    int c = wn * 64 + ni * 8 + g;
                    bf[ni][0] = Ws[kw + tg][c]; bf[ni][1] = Ws[kw + tg + 4][c];
                }
#pragma unroll
                for (int mi = 0; mi < 2; mi++)
#pragma unroll
                    for (int ni = 0; ni < 8; ni++) mma8(acc[mi][ni], a[mi], bf[ni]);
            }
            __syncthreads();
        }
        if (layer == 1) {
#pragma unroll
            for (int mi = 0; mi < 2; mi++) {
                int r0 = wm * 32 + mi * 16 + g;
#pragma unroll
                for (int ni = 0; ni < 8; ni++) {
                    int c0 = wn * 64 + ni * 8 + 2 * tg;
                    Hs[r0][c0]       = f2tf(gelu_t(acc[mi][ni][0] + sb[128 + c0]));
                    Hs[r0][c0 + 1]   = f2tf(gelu_t(acc[mi][ni][1] + sb[128 + c0 + 1]));
                    Hs[r0 + 8][c0]   = f2tf(gelu_t(acc[mi][ni][2] + sb[128 + c0]));
                    Hs[r0 + 8][c0 + 1] = f2tf(gelu_t(acc[mi][ni][3] + sb[128 + c0 + 1]));
                }
            }
        } else {
#pragma unroll
            for (int mi = 0; mi < 2; mi++) {
                int r0 = wm * 32 + mi * 16 + g;
#pragma unroll
                for (int ni = 0; ni < 8; ni++) {
                    int c0 = wn * 64 + ni * 8 + 2 * tg;
                    Hs[r0][c0]       = __float_as_uint(acc[mi][ni][0] + sb[256 + c0]);
                    Hs[r0][c0 + 1]   = __float_as_uint(acc[mi][ni][1] + sb[256 + c0 + 1]);
                    Hs[r0 + 8][c0]   = __float_as_uint(acc[mi][ni][2] + sb[256 + c0]);
                    Hs[r0 + 8][c0 + 1] = __float_as_uint(acc[mi][ni][3] + sb[256 + c0 + 1]);
                }
            }
        }
        __syncthreads();
    }

    // residual + LN3 per edge row; warp handles rows warp, warp+8, ...
    for (int r = warp; r < 128; r += 8) {
        long base = (e0 + r) * Hc;
        float x[4], s = 0.f, s2 = 0.f;
#pragma unroll
        for (int q = 0; q < 4; q++) {
            int c = lane + 32 * q;
            x[q] = __uint_as_float(Hs[r][c]) + hE[base + c];
            s += x[q]; s2 += x[q] * x[q];
        }
#pragma unroll
        for (int off = 16; off; off >>= 1) {
            s  += __shfl_xor_sync(0xffffffffu, s,  off);
            s2 += __shfl_xor_sync(0xffffffffu, s2, off);
        }
        float mu  = s * (1.0f / 128.0f);
        float var = s2 * (1.0f / 128.0f) - mu * mu;
        float inv = rsqrtf(var + EPSLN);
#pragma unroll
        for (int q = 0; q < 4; q++) {
            int c = lane + 32 * q;
            outE[base + c] = (x[q] - mu) * inv * sb[384 + c] + sb[512 + c];
        }
    }
}

// ======================= launch =======================
extern "C" void kernel_launch(void* const* d_in, const int* in_sizes, int n_in,
                              void* d_out, int out_size)
{
    (void)in_sizes; (void)n_in; (void)out_size;
    const float* hV    = (const float*)d_in[0];
    const float* hE    = (const float*)d_in[1];
    const float* maskV = (const float*)d_in[2];
    const int*   Eidx  = (const int*)d_in[3];
    const float* mA    = (const float*)d_in[4];
    const float* W1w = (const float*)d_in[5],  *W1b = (const float*)d_in[6];
    const float* W2w = (const float*)d_in[7],  *W2b = (const float*)d_in[8];
    const float* W3w = (const float*)d_in[9],  *W3b = (const float*)d_in[10];
    const float* W11w = (const float*)d_in[11], *W11b = (const float*)d_in[12];
    const float* W12w = (const float*)d_in[13], *W12b = (const float*)d_in[14];
    const float* W13w = (const float*)d_in[15], *W13b = (const float*)d_in[16];
    const float* Winw = (const float*)d_in[17], *Winb = (const float*)d_in[18];
    const float* Woutw = (const float*)d_in[19], *Woutb = (const float*)d_in[20];
    const float* ln1g = (const float*)d_in[21], *ln1b = (const float*)d_in[22];
    const float* ln2g = (const float*)d_in[23], *ln2b = (const float*)d_in[24];
    const float* ln3g = (const float*)d_in[25], *ln3b = (const float*)d_in[26];

    float* outV = (float*)d_out;            // [8192,128]
    float* outE = outV + VOUT;              // [393216,128]

    cudaFuncSetAttribute(k_stage1, cudaFuncAttributeMaxDynamicSharedMemorySize, SM1);
    cudaFuncSetAttribute(k_stage2, cudaFuncAttributeMaxDynamicSharedMemorySize, SM2);
    cudaFuncSetAttribute(k_stage3, cudaFuncAttributeMaxDynamicSharedMemorySize, SM3);

    k_stage1<<<BN / 4, 256, SM1>>>(hV, hE, mA, W1w, W1b, W2w, W2b, W3w, W3b, ln1g, ln1b);
    k_stage2<<<BN / 32, 256, SM2>>>(maskV, Winw, Winb, Woutw, Woutb, ln2g, ln2b, outV);
    k_stage3<<<(int)(ETOT / 128), 256, SM3>>>(outV, hE, Eidx,
                                              W11w, W11b, W12w, W12b, W13w, W13b,
                                              ln3g, ln3b, outE);
}

// round 2
// speedup vs baseline: 3.6189x; 3.6189x over previous
#include <cuda_runtime.h>
#include <cstdint>
#include <math.h>

// ---------------------------------------------------------------------------
// DecLayer: B=4, N=2048, K=48, H=IN=128
// Round 2: raw-fp32-as-tf32 mma (no cvt), cp.async double-buffered staging,
//          hV-part hoisting (P1/P3 precompute), 512-thread blocks,
//          tanh.approx gelu.
// ---------------------------------------------------------------------------

#define EPSLN 1e-5f

static constexpr int Kc = 48, Hc = 128;
static constexpr int BN = 8192;                 // 4*2048 nodes
static constexpr long ETOT = (long)BN * Kc;     // 393216 edges
static constexpr long VOUT = (long)BN * Hc;

__device__ float g_hV1[BN * Hc];                // h_V after LN1
__device__ float g_P1[BN * Hc];                 // hV  @ W1[0:128]
__device__ float g_P3[BN * Hc];                 // hV2 @ W11[0:128]

// ------------------------------ helpers -----------------------------------
static __device__ __forceinline__ uint32_t s2u(const void* p) {
    return (uint32_t)__cvta_generic_to_shared(p);
}
static __device__ __forceinline__ void cp16(uint32_t s, const void* g) {
    asm volatile("cp.async.cg.shared.global [%0], [%1], 16;" :: "r"(s), "l"(g));
}
static __device__ __forceinline__ void cp_commit() {
    asm volatile("cp.async.commit_group;");
}
template <int N>
static __device__ __forceinline__ void cp_wait() {
    asm volatile("cp.async.wait_group %0;" :: "n"(N));
}

static __device__ __forceinline__ void mma8(float* d, const uint32_t* a, const uint32_t* b) {
    asm volatile(
        "mma.sync.aligned.m16n8k8.row.col.f32.tf32.tf32.f32 "
        "{%0,%1,%2,%3},{%4,%5,%6,%7},{%8,%9},{%0,%1,%2,%3};"
        : "+f"(d[0]), "+f"(d[1]), "+f"(d[2]), "+f"(d[3])
        : "r"(a[0]), "r"(a[1]), "r"(a[2]), "r"(a[3]), "r"(b[0]), "r"(b[1]));
}

static __device__ __forceinline__ float gelu_t(float x) {
    float z = 0.7978845608028654f * (x + 0.044715f * x * x * x);
    float t;
    asm("tanh.approx.f32 %0, %1;" : "=f"(t) : "f"(z));
    return 0.5f * x * (1.0f + t);
}

// warp-tile mma: MI x16 rows, NI x8 cols, 32 K per call (4 ks-steps of 8)
template <int MI, int NI>
static __device__ __forceinline__ void mma_tile(
    float (*acc)[NI][4],
    const uint32_t* __restrict__ Aw, int astr, int ak,   // A: + (mi*16+g)*astr + k
    const uint32_t* __restrict__ Wc,                     // W: + (k)*136 + ni*8+g
    int g, int tg)
{
#pragma unroll
    for (int ks = 0; ks < 4; ks++) {
        const int kk = ak + ks * 8;
        const int kw = ks * 8;
        uint32_t a[MI][4], b[NI][2];
#pragma unroll
        for (int mi = 0; mi < MI; mi++) {
            const uint32_t* Ar = Aw + (mi * 16 + g) * astr + kk + tg;
            a[mi][0] = Ar[0];
            a[mi][1] = Ar[8 * astr];
            a[mi][2] = Ar[4];
            a[mi][3] = Ar[8 * astr + 4];
        }
#pragma unroll
        for (int ni = 0; ni < NI; ni++) {
            const uint32_t* Wr = Wc + (kw + tg) * 136 + ni * 8 + g;
            b[ni][0] = Wr[0];
            b[ni][1] = Wr[4 * 136];
        }
#pragma unroll
        for (int mi = 0; mi < MI; mi++)
#pragma unroll
            for (int ni = 0; ni < NI; ni++) mma8(acc[mi][ni], a[mi], b[ni]);
    }
}

// ----------------------- smem layouts (float words) ------------------------
static constexpr int HS_STR = 132, XS_STR = 44, WS_STR = 136;
static constexpr int XS_BUF = 192 * XS_STR;    // 8448
static constexpr int WS_BUF = 32 * WS_STR;     // 4352

static constexpr int OFF_XS = 192 * HS_STR;            // 25344
static constexpr int OFF_WS = OFF_XS + 2 * XS_BUF;     // 42240
static constexpr int OFF_PS = OFF_WS + 2 * WS_BUF;     // 50944
static constexpr int OFF_SB = OFF_PS + 512;            // 51456
static constexpr int OFF_MK = OFF_SB + 640;            // 52096
static constexpr int OFF_P  = OFF_MK + 192;            // 52288
static constexpr int SM13   = (OFF_P + 512) * 4;       // 211200 B

static constexpr int PG_OFF_WS = 128 * HS_STR;                 // 16896
static constexpr int SMPG      = (PG_OFF_WS + 2 * WS_BUF) * 4; // 102400 B

// =================== small GEMM: Out[8192,128] = X @ W[0:128,:] ============
__global__ __launch_bounds__(256, 1) void k_pgemm(
    const float* __restrict__ X, const float* __restrict__ W, int dstSel)
{
    extern __shared__ float sm[];
    float* Xs = sm;
    float* Ws = sm + PG_OFF_WS;
    const uint32_t* Xu = (const uint32_t*)Xs;
    const uint32_t* Wu = (const uint32_t*)Ws;
    float* Out = dstSel ? g_P3 : g_P1;

    const int tid = threadIdx.x, warp = tid >> 5, lane = tid & 31;
    const int g = lane >> 2, tg = lane & 3;
    const int wm = warp >> 1, wn = warp & 1;      // 4 x 2 warp grid, tile 32x64
    const long r0g = (long)blockIdx.x * 128;

    const uint32_t uXs = s2u(Xs), uWs = s2u(Ws);

    auto stage_w = [&](int kcc, int buf) {
        uint32_t base = uWs + buf * WS_BUF * 4;
        for (int i = tid; i < 1024; i += 256) {
            int r = i >> 5, c4 = (i & 31) << 2;
            cp16(base + (r * WS_STR + c4) * 4, W + (kcc * 32 + r) * 128 + c4);
        }
    };

    // prologue: whole X + W chunk0 -> group0, W chunk1 -> group1
    for (int i = tid; i < 4096; i += 256) {
        int r = i >> 5, c4 = (i & 31) << 2;
        cp16(uXs + (r * HS_STR + c4) * 4, X + (r0g + r) * Hc + c4);
    }
    stage_w(0, 0);
    cp_commit();
    stage_w(1, 1);
    cp_commit();

    float acc[2][8][4];
#pragma unroll
    for (int mi = 0; mi < 2; mi++)
#pragma unroll
        for (int ni = 0; ni < 8; ni++)
#pragma unroll
            for (int q = 0; q < 4; q++) acc[mi][ni][q] = 0.f;

    cp_wait<1>();
    __syncthreads();
    for (int kc = 0; kc < 4; kc++) {
        mma_tile<2, 8>(acc, Xu + wm * 32 * HS_STR, HS_STR, kc * 32,
                       Wu + (kc & 1) * WS_BUF + wn * 64, g, tg);
        __syncthreads();
        if (kc + 2 < 4) { stage_w(kc + 2, kc & 1); cp_commit(); }
        if (kc + 1 < 4) {
            if (kc + 2 < 4) cp_wait<1>(); else cp_wait<0>();
            __syncthreads();
        }
    }
#pragma unroll
    for (int mi = 0; mi < 2; mi++) {
        int rr = wm * 32 + mi * 16 + g;
#pragma unroll
        for (int ni = 0; ni < 8; ni++) {
            int c0 = wn * 64 + ni * 8 + 2 * tg;
            *(float2*)(Out + (r0g + rr) * Hc + c0) =
                make_float2(acc[mi][ni][0], acc[mi][ni][1]);
            *(float2*)(Out + (r0g + rr + 8) * Hc + c0) =
                make_float2(acc[mi][ni][2], acc[mi][ni][3]);
        }
    }
}

// ======================= Stage 1: node message + LN1 =======================
// block: 4 nodes = 192 edge rows, 512 threads (16 warps, grid 4x4, tile 48x32)
__global__ __launch_bounds__(512, 1) void k_stage1(
    const float* __restrict__ hV, const float* __restrict__ hE,
    const float* __restrict__ mA,
    const float* __restrict__ W1e, const float* __restrict__ b1,
    const float* __restrict__ W2,  const float* __restrict__ b2,
    const float* __restrict__ W3,  const float* __restrict__ b3,
    const float* __restrict__ lng, const float* __restrict__ lnb)
{
    extern __shared__ float sm[];
    float* Hs = sm;
    float* Xs = sm + OFF_XS;
    float* Ws = sm + OFF_WS;
    float* Ps = sm + OFF_PS;
    float* sb = sm + OFF_SB;
    float* smask = sm + OFF_MK;
    float* Pln = sm + OFF_P;
    const uint32_t* Hu = (const uint32_t*)Hs;
    const uint32_t* Xu = (const uint32_t*)Xs;
    const uint32_t* Wu = (const uint32_t*)Ws;

    const int tid = threadIdx.x, warp = tid >> 5, lane = tid & 31;
    const int g = lane >> 2, tg = lane & 3;
    const int wm = warp >> 2, wn = warp & 3;
    const int node0 = blockIdx.x * 4;
    const long e0 = (long)node0 * Kc;

    const uint32_t uXs = s2u(Xs), uWs = s2u(Ws), uPs = s2u(Ps);

    auto stage_w = [&](const float* W, int kcc, int buf) {
        uint32_t base = uWs + buf * WS_BUF * 4;
        for (int i = tid; i < 1024; i += 512) {
            int r = i >> 5, c4 = (i & 31) << 2;
            cp16(base + (r * WS_STR + c4) * 4, W + (kcc * 32 + r) * 128 + c4);
        }
    };
    auto stage_x = [&](int kcc, int buf) {
        uint32_t base = uXs + buf * XS_BUF * 4;
        for (int i = tid; i < 1536; i += 512) {
            int r = i >> 3, c4 = (i & 7) << 2;
            cp16(base + (r * XS_STR + c4) * 4, hE + (e0 + r) * Hc + kcc * 32 + c4);
        }
    };

    // prologue: Ps + X0 + W0 -> group0; X1 + W1 -> group1
    for (int i = tid; i < 128; i += 512)
        cp16(uPs + i * 16, g_P1 + (long)node0 * Hc + i * 4);
    stage_x(0, 0);
    stage_w(W1e, 0, 0);
    cp_commit();
    stage_x(1, 1);
    stage_w(W1e, 1, 1);
    cp_commit();

    for (int i = tid; i < 128; i += 512) {
        sb[i] = b1[i]; sb[128 + i] = b2[i]; sb[256 + i] = b3[i];
        sb[384 + i] = lng[i]; sb[512 + i] = lnb[i];
    }
    if (tid < 192) smask[tid] = mA[e0 + tid];

    float acc[3][4][4];

    auto epi_gelu = [&](const float* bias) {
#pragma unroll
        for (int mi = 0; mi < 3; mi++) {
            int r0 = wm * 48 + mi * 16 + g;
#pragma unroll
            for (int ni = 0; ni < 4; ni++) {
                int c0 = wn * 32 + ni * 8 + 2 * tg;
                float b0 = bias[c0], b1v = bias[c0 + 1];
                *(float2*)(Hs + r0 * HS_STR + c0) =
                    make_float2(gelu_t(acc[mi][ni][0] + b0), gelu_t(acc[mi][ni][1] + b1v));
                *(float2*)(Hs + (r0 + 8) * HS_STR + c0) =
                    make_float2(gelu_t(acc[mi][ni][2] + b0), gelu_t(acc[mi][ni][3] + b1v));
            }
        }
    };

    cp_wait<1>();
    __syncthreads();

    // init acc from Ps (all 48 rows of a warp tile belong to node wm)
#pragma unroll
    for (int ni = 0; ni < 4; ni++) {
        int c0 = wn * 32 + ni * 8 + 2 * tg;
        float v0 = Ps[wm * 128 + c0], v1 = Ps[wm * 128 + c0 + 1];
#pragma unroll
        for (int mi = 0; mi < 3; mi++) {
            acc[mi][ni][0] = v0; acc[mi][ni][1] = v1;
            acc[mi][ni][2] = v0; acc[mi][ni][3] = v1;
        }
    }

    // ---- layer 1: K=128 over hE only
    for (int kc = 0; kc < 4; kc++) {
        mma_tile<3, 4>(acc, Xu + (kc & 1) * XS_BUF + wm * 48 * XS_STR, XS_STR, 0,
                       Wu + (kc & 1) * WS_BUF + wn * 32, g, tg);
        __syncthreads();
        if (kc + 2 < 4) { stage_x(kc + 2, kc & 1); stage_w(W1e, kc + 2, kc & 1); cp_commit(); }
        if (kc + 1 < 4) {
            if (kc + 2 < 4) cp_wait<1>(); else cp_wait<0>();
            __syncthreads();
        }
    }
    epi_gelu(sb);

    // ---- layers 2, 3 on Hs in place
#pragma unroll 1
    for (int layer = 1; layer < 3; layer++) {
        const float* Wl = (layer == 1) ? W2 : W3;
#pragma unroll
        for (int mi = 0; mi < 3; mi++)
#pragma unroll
            for (int ni = 0; ni < 4; ni++)
#pragma unroll
                for (int q = 0; q < 4; q++) acc[mi][ni][q] = 0.f;
        stage_w(Wl, 0, 0); cp_commit();
        stage_w(Wl, 1, 1); cp_commit();
        cp_wait<1>();
        __syncthreads();
        for (int kc = 0; kc < 4; kc++) {
            mma_tile<3, 4>(acc, Hu + wm * 48 * HS_STR, HS_STR, kc * 32,
                           Wu + (kc & 1) * WS_BUF + wn * 32, g, tg);
            __syncthreads();
            if (kc + 2 < 4) { stage_w(Wl, kc + 2, kc & 1); cp_commit(); }
            if (kc + 1 < 4) {
                if (kc + 2 < 4) cp_wait<1>(); else cp_wait<0>();
                __syncthreads();
            }
        }
        if (layer == 1) {
            epi_gelu(sb + 128);
        } else {
#pragma unroll
            for (int mi = 0; mi < 3; mi++) {
                int r0 = wm * 48 + mi * 16 + g;
                float m0 = smask[r0], m1 = smask[r0 + 8];
#pragma unroll
                for (int ni = 0; ni < 4; ni++) {
                    int c0 = wn * 32 + ni * 8 + 2 * tg;
                    float b0 = sb[256 + c0], b1v = sb[256 + c0 + 1];
                    *(float2*)(Hs + r0 * HS_STR + c0) =
                        make_float2((acc[mi][ni][0] + b0) * m0, (acc[mi][ni][1] + b1v) * m0);
                    *(float2*)(Hs + (r0 + 8) * HS_STR + c0) =
                        make_float2((acc[mi][ni][2] + b0) * m1, (acc[mi][ni][3] + b1v) * m1);
                }
            }
        }
    }
    __syncthreads();

    // sum over K=48, residual, LN1 -> g_hV1
    {
        int nn = tid >> 7, c = tid & 127;
        float s = 0.f;
#pragma unroll 8
        for (int j = 0; j < 48; j++) s += Hs[(nn * 48 + j) * HS_STR + c];
        Pln[nn * 128 + c] = hV[(long)(node0 + nn) * Hc + c] + s * (1.0f / 30.0f);
    }
    __syncthreads();
    if (warp < 4) {
        int nn = warp;
        float x[4], s = 0.f, s2 = 0.f;
#pragma unroll
        for (int q = 0; q < 4; q++) {
            x[q] = Pln[nn * 128 + lane + 32 * q];
            s += x[q]; s2 += x[q] * x[q];
        }
#pragma unroll
        for (int off = 16; off; off >>= 1) {
            s  += __shfl_xor_sync(0xffffffffu, s,  off);
            s2 += __shfl_xor_sync(0xffffffffu, s2, off);
        }
        float mu  = s * (1.0f / 128.0f);
        float var = s2 * (1.0f / 128.0f) - mu * mu;
        float inv = rsqrtf(var + EPSLN);
#pragma unroll
        for (int q = 0; q < 4; q++) {
            int c = lane + 32 * q;
            g_hV1[(long)(node0 + nn) * Hc + c] =
                (x[q] - mu) * inv * sb[384 + c] + sb[512 + c];
        }
    }
}

// ======================= Stage 2: FFN + LN2 + mask_V =======================
static constexpr int SM2 = (128 * 36 + 512 * 36 + 32 * 128 + 896) * 4;

__global__ __launch_bounds__(256, 1) void k_stage2(
    const float* __restrict__ maskV,
    const float* __restrict__ Win,  const float* __restrict__ bin,
    const float* __restrict__ Wout, const float* __restrict__ bout,
    const float* __restrict__ lng,  const float* __restrict__ lnb,
    float* __restrict__ outV)
{
    extern __shared__ float smf[];
    float (*HT)[36] = reinterpret_cast<float(*)[36]>(smf);
    float (*TT)[36] = reinterpret_cast<float(*)[36]>(smf + 128 * 36);
    float* P  = smf + (128 + 512) * 36;
    float* sb = P + 32 * 128;

    const int tid = threadIdx.x, warp = tid >> 5, lane = tid & 31;
    const int node0 = blockIdx.x * 32;

    for (int i = tid; i < 512; i += 256) sb[i] = bin[i];
    for (int i = tid; i < 128; i += 256) {
        sb[512 + i] = bout[i]; sb[640 + i] = lng[i]; sb[768 + i] = lnb[i];
    }
    for (int i = tid; i < 32 * 128; i += 256) {
        int m = i >> 7, k = i & 127;
        HT[k][m] = g_hV1[(long)(node0 + m) * Hc + k];
    }
    __syncthreads();

    float a0[32], a1[32];
#pragma unroll
    for (int m = 0; m < 32; m++) { a0[m] = 0.f; a1[m] = 0.f; }
    const int j0 = tid, j1 = tid + 256;
    for (int k = 0; k < 128; k++) {
        float w0 = __ldg(&Win[k * 512 + j0]);
        float w1 = __ldg(&Win[k * 512 + j1]);
        const float4* hp = reinterpret_cast<const float4*>(&HT[k][0]);
#pragma unroll
        for (int q = 0; q < 8; q++) {
            float4 h = hp[q];
            a0[4 * q + 0] += h.x * w0; a0[4 * q + 1] += h.y * w0;
            a0[4 * q + 2] += h.z * w0; a0[4 * q + 3] += h.w * w0;
            a1[4 * q + 0] += h.x * w1; a1[4 * q + 1] += h.y * w1;
            a1[4 * q + 2] += h.z * w1; a1[4 * q + 3] += h.w * w1;
        }
    }
    float bj0 = sb[j0], bj1 = sb[j1];
#pragma unroll
    for (int q = 0; q < 8; q++) {
        float4 v0, v1;
        v0.x = gelu_t(a0[4 * q + 0] + bj0); v0.y = gelu_t(a0[4 * q + 1] + bj0);
        v0.z = gelu_t(a0[4 * q + 2] + bj0); v0.w = gelu_t(a0[4 * q + 3] + bj0);
        v1.x = gelu_t(a1[4 * q + 0] + bj1); v1.y = gelu_t(a1[4 * q + 1] + bj1);
        v1.z = gelu_t(a1[4 * q + 2] + bj1); v1.w = gelu_t(a1[4 * q + 3] + bj1);
        *reinterpret_cast<float4*>(&TT[j0][4 * q]) = v0;
        *reinterpret_cast<float4*>(&TT[j1][4 * q]) = v1;
    }
    __syncthreads();

    const int grp = tid >> 7, col = tid & 127;
    float c16[16];
#pragma unroll
    for (int m = 0; m < 16; m++) c16[m] = 0.f;
    for (int k = 0; k < 512; k++) {
        float w = __ldg(&Wout[k * 128 + col]);
        const float4* tp = reinterpret_cast<const float4*>(&TT[k][grp * 16]);
#pragma unroll
        for (int q = 0; q < 4; q++) {
            float4 t = tp[q];
            c16[4 * q + 0] += t.x * w; c16[4 * q + 1] += t.y * w;
            c16[4 * q + 2] += t.z * w; c16[4 * q + 3] += t.w * w;
        }
    }
#pragma unroll
    for (int m = 0; m < 16; m++) {
        int node = grp * 16 + m;
        P[node * 128 + col] = HT[col][node] + c16[m] + sb[512 + col];
    }
    __syncthreads();

    for (int q4 = 0; q4 < 4; q4++) {
        int node = warp * 4 + q4;
        float x[4], s = 0.f, s2 = 0.f;
#pragma unroll
        for (int q = 0; q < 4; q++) {
            x[q] = P[node * 128 + lane + 32 * q];
            s += x[q]; s2 += x[q] * x[q];
        }
#pragma unroll
        for (int off = 16; off; off >>= 1) {
            s  += __shfl_xor_sync(0xffffffffu, s,  off);
            s2 += __shfl_xor_sync(0xffffffffu, s2, off);
        }
        float mu  = s * (1.0f / 128.0f);
        float var = s2 * (1.0f / 128.0f) - mu * mu;
        float inv = rsqrtf(var + EPSLN);
        float mv  = maskV[node0 + node];
#pragma unroll
        for (int q = 0; q < 4; q++) {
            int c = lane + 32 * q;
            outV[(long)(node0 + node) * Hc + c] =
                mv * ((x[q] - mu) * inv * sb[640 + c] + sb[768 + c]);
        }
    }
}

// ======================= Stage 3: edge update + LN3 =======================
// block: 4 nodes = 192 edge rows (node-aligned), same shape as stage1.
__global__ __launch_bounds__(512, 1) void k_stage3(
    const float* __restrict__ hV2, const float* __restrict__ hE,
    const int* __restrict__ Eidx,
    const float* __restrict__ W11m, const float* __restrict__ b11,
    const float* __restrict__ W12,  const float* __restrict__ b12,
    const float* __restrict__ W13,  const float* __restrict__ b13,
    const float* __restrict__ lng,  const float* __restrict__ lnb,
    float* __restrict__ outE)
{
    extern __shared__ float sm[];
    float* Hs = sm;
    float* Xs = sm + OFF_XS;
    float* Ws = sm + OFF_WS;
    float* Ps = sm + OFF_PS;
    float* sb = sm + OFF_SB;
    int* rBs = (int*)(sm + OFF_MK);
    const uint32_t* Hu = (const uint32_t*)Hs;
    const uint32_t* Xu = (const uint32_t*)Xs;
    const uint32_t* Wu = (const uint32_t*)Ws;

    const int tid = threadIdx.x, warp = tid >> 5, lane = tid & 31;
    const int g = lane >> 2, tg = lane & 3;
    const int wm = warp >> 2, wn = warp & 3;
    const int node0 = blockIdx.x * 4;
    const long e0 = (long)node0 * Kc;

    const uint32_t uXs = s2u(Xs), uWs = s2u(Ws), uPs = s2u(Ps);

    if (tid < 192) {
        long e = e0 + tid;
        int bn = (int)(e / Kc);
        rBs[tid] = ((bn >> 11) << 11) + Eidx[e];
    }

    auto stage_w = [&](const float* W, int kcc, int buf) {
        uint32_t base = uWs + buf * WS_BUF * 4;
        for (int i = tid; i < 1024; i += 512) {
            int r = i >> 5, c4 = (i & 31) << 2;
            cp16(base + (r * WS_STR + c4) * 4, W + (kcc * 32 + r) * 128 + c4);
        }
    };
    auto stage_x = [&](int kcc, int buf) {
        uint32_t base = uXs + buf * XS_BUF * 4;
        const int colbase = kcc * 32;
        for (int i = tid; i < 1536; i += 512) {
            int r = i >> 3, c4 = (i & 7) << 2;
            int col = colbase + c4;
            const float* src = (col < 128)
                ? (hE + (e0 + r) * Hc + col)
                : (hV2 + (long)rBs[r] * Hc + (col - 128));
            cp16(base + (r * XS_STR + c4) * 4, src);
        }
    };

    // prologue (chunks 0 and 1 are hE-only: no rBs dependence)
    for (int i = tid; i < 128; i += 512)
        cp16(uPs + i * 16, g_P3 + (long)node0 * Hc + i * 4);
    stage_x(0, 0);
    stage_w(W11m, 0, 0);
    cp_commit();
    stage_x(1, 1);
    stage_w(W11m, 1, 1);
    cp_commit();

    for (int i = tid; i < 128; i += 512) {
        sb[i] = b11[i]; sb[128 + i] = b12[i]; sb[256 + i] = b13[i];
        sb[384 + i] = lng[i]; sb[512 + i] = lnb[i];
    }

    float acc[3][4][4];

    auto epi_gelu = [&](const float* bias) {
#pragma unroll
        for (int mi = 0; mi < 3; mi++) {
            int r0 = wm * 48 + mi * 16 + g;
#pragma unroll
            for (int ni = 0; ni < 4; ni++) {
                int c0 = wn * 32 + ni * 8 + 2 * tg;
                float b0 = bias[c0], b1v = bias[c0 + 1];
                *(float2*)(Hs + r0 * HS_STR + c0) =
                    make_float2(gelu_t(acc[mi][ni][0] + b0), gelu_t(acc[mi][ni][1] + b1v));
                *(float2*)(Hs + (r0 + 8) * HS_STR + c0) =
                    make_float2(gelu_t(acc[mi][ni][2] + b0), gelu_t(acc[mi][ni][3] + b1v));
            }
        }
    };

    cp_wait<1>();
    __syncthreads();

#pragma unroll
    for (int ni = 0; ni < 4; ni++) {
        int c0 = wn * 32 + ni * 8 + 2 * tg;
        float v0 = Ps[wm * 128 + c0], v1 = Ps[wm * 128 + c0 + 1];
#pragma unroll
        for (int mi = 0; mi < 3; mi++) {
            acc[mi][ni][0] = v0; acc[mi][ni][1] = v1;
            acc[mi][ni][2] = v0; acc[mi][ni][3] = v1;
        }
    }

    // ---- layer 1: K=256 (hE cols 0-127, gathered hV2 cols 128-255)
    for (int kc = 0; kc < 8; kc++) {
        mma_tile<3, 4>(acc, Xu + (kc & 1) * XS_BUF + wm * 48 * XS_STR, XS_STR, 0,
                       Wu + (kc & 1) * WS_BUF + wn * 32, g, tg);
        __syncthreads();
        if (kc + 2 < 8) { stage_x(kc + 2, kc & 1); stage_w(W11m, kc + 2, kc & 1); cp_commit(); }
        if (kc + 1 < 8) {
            if (kc + 2 < 8) cp_wait<1>(); else cp_wait<0>();
            __syncthreads();
        }
    }
    epi_gelu(sb);

    // ---- layers 2, 3
#pragma unroll 1
    for (int layer = 1; layer < 3; layer++) {
        const float* Wl = (layer == 1) ? W12 : W13;
#pragma unroll
        for (int mi = 0; mi < 3; mi++)
#pragma unroll
            for (int ni = 0; ni < 4; ni++)
#pragma unroll
                for (int q = 0; q < 4; q++) acc[mi][ni][q] = 0.f;
        stage_w(Wl, 0, 0); cp_commit();
        stage_w(Wl, 1, 1); cp_commit();
        cp_wait<1>();
        __syncthreads();
        for (int kc = 0; kc < 4; kc++) {
            mma_tile<3, 4>(acc, Hu + wm * 48 * HS_STR, HS_STR, kc * 32,
                           Wu + (kc & 1) * WS_BUF + wn * 32, g, tg);
            __syncthreads();
            if (kc + 2 < 4) { stage_w(Wl, kc + 2, kc & 1); cp_commit(); }
            if (kc + 1 < 4) {
                if (kc + 2 < 4) cp_wait<1>(); else cp_wait<0>();
                __syncthreads();
            }
        }
        if (layer == 1) {
            epi_gelu(sb + 128);
        } else {
#pragma unroll
            for (int mi = 0; mi < 3; mi++) {
                int r0 = wm * 48 + mi * 16 + g;
#pragma unroll
                for (int ni = 0; ni < 4; ni++) {
                    int c0 = wn * 32 + ni * 8 + 2 * tg;
                    float b0 = sb[256 + c0], b1v = sb[256 + c0 + 1];
                    *(float2*)(Hs + r0 * HS_STR + c0) =
                        make_float2(acc[mi][ni][0] + b0, acc[mi][ni][1] + b1v);
                    *(float2*)(Hs + (r0 + 8) * HS_STR + c0) =
                        make_float2(acc[mi][ni][2] + b0, acc[mi][ni][3] + b1v);
                }
            }
        }
    }
    __syncthreads();

    // residual + LN3 per edge row
    for (int r = warp; r < 192; r += 16) {
        long base = (e0 + r) * Hc;
        float x[4], s = 0.f, s2 = 0.f;
#pragma unroll
        for (int q = 0; q < 4; q++) {
            int c = lane + 32 * q;
            x[q] = Hs[r * HS_STR + c] + hE[base + c];
            s += x[q]; s2 += x[q] * x[q];
        }
#pragma unroll
        for (int off = 16; off; off >>= 1) {
            s  += __shfl_xor_sync(0xffffffffu, s,  off);
            s2 += __shfl_xor_sync(0xffffffffu, s2, off);
        }
        float mu  = s * (1.0f / 128.0f);
        float var = s2 * (1.0f / 128.0f) - mu * mu;
        float inv = rsqrtf(var + EPSLN);
#pragma unroll
        for (int q = 0; q < 4; q++) {
            int c = lane + 32 * q;
            outE[base + c] = (x[q] - mu) * inv * sb[384 + c] + sb[512 + c];
        }
    }
}

// ======================= launch =======================
extern "C" void kernel_launch(void* const* d_in, const int* in_sizes, int n_in,
                              void* d_out, int out_size)
{
    (void)in_sizes; (void)n_in; (void)out_size;
    const float* hV    = (const float*)d_in[0];
    const float* hE    = (const float*)d_in[1];
    const float* maskV = (const float*)d_in[2];
    const int*   Eidx  = (const int*)d_in[3];
    const float* mA    = (const float*)d_in[4];
    const float* W1w = (const float*)d_in[5],  *W1b = (const float*)d_in[6];
    const float* W2w = (const float*)d_in[7],  *W2b = (const float*)d_in[8];
    const float* W3w = (const float*)d_in[9],  *W3b = (const float*)d_in[10];
    const float* W11w = (const float*)d_in[11], *W11b = (const float*)d_in[12];
    const float* W12w = (const float*)d_in[13], *W12b = (const float*)d_in[14];
    const float* W13w = (const float*)d_in[15], *W13b = (const float*)d_in[16];
    const float* Winw = (const float*)d_in[17], *Winb = (const float*)d_in[18];
    const float* Woutw = (const float*)d_in[19], *Woutb = (const float*)d_in[20];
    const float* ln1g = (const float*)d_in[21], *ln1b = (const float*)d_in[22];
    const float* ln2g = (const float*)d_in[23], *ln2b = (const float*)d_in[24];
    const float* ln3g = (const float*)d_in[25], *ln3b = (const float*)d_in[26];

    float* outV = (float*)d_out;            // [8192,128]
    float* outE = outV + VOUT;              // [393216,128]

    cudaFuncSetAttribute(k_pgemm,  cudaFuncAttributeMaxDynamicSharedMemorySize, SMPG);
    cudaFuncSetAttribute(k_stage1, cudaFuncAttributeMaxDynamicSharedMemorySize, SM13);
    cudaFuncSetAttribute(k_stage2, cudaFuncAttributeMaxDynamicSharedMemorySize, SM2);
    cudaFuncSetAttribute(k_stage3, cudaFuncAttributeMaxDynamicSharedMemorySize, SM13);

    k_pgemm<<<64, 256, SMPG>>>(hV, W1w, 0);
    k_stage1<<<2048, 512, SM13>>>(hV, hE, mA, W1w + 128 * 128, W1b,
                                  W2w, W2b, W3w, W3b, ln1g, ln1b);
    k_stage2<<<256, 256, SM2>>>(maskV, Winw, Winb, Woutw, Woutb, ln2g, ln2b, outV);
    k_pgemm<<<64, 256, SMPG>>>(outV, W11w, 1);
    k_stage3<<<2048, 512, SM13>>>(outV, hE, Eidx, g_P3 /*unused placeholder safety*/ == g_P3 ? W11w + 128 * 128 : W11w, W11b,
                                  W12w, W12b, W13w, W13b, ln3g, ln3b, outE);
}

// round 3
// speedup vs baseline: 3.7212x; 1.0283x over previous
#include <cuda_runtime.h>
#include <cstdint>
#include <math.h>

// ---------------------------------------------------------------------------
// DecLayer: B=4, N=2048, K=48, H=IN=128
// Round 3: 2-node blocks (96 rows, 256 thr), A-resident-in-Hs layers,
//          2 CTAs/SM, gather phase via Hs restage, weight double-buffer.
// ---------------------------------------------------------------------------

#define EPSLN 1e-5f

static constexpr int Kc = 48, Hc = 128;
static constexpr int BN = 8192;
static constexpr long VOUT = (long)BN * Hc;

__device__ float g_hV1[BN * Hc];                // h_V after LN1
__device__ float g_P1[BN * Hc];                 // hV  @ W1[0:128]
__device__ float g_P3[BN * Hc];                 // hV2 @ W11[0:128]

// ------------------------------ helpers -----------------------------------
static __device__ __forceinline__ uint32_t s2u(const void* p) {
    return (uint32_t)__cvta_generic_to_shared(p);
}
static __device__ __forceinline__ void cp16(uint32_t s, const void* g) {
    asm volatile("cp.async.cg.shared.global [%0], [%1], 16;" :: "r"(s), "l"(g));
}
static __device__ __forceinline__ void cp_commit() {
    asm volatile("cp.async.commit_group;");
}
template <int N>
static __device__ __forceinline__ void cp_wait() {
    asm volatile("cp.async.wait_group %0;" :: "n"(N));
}

static __device__ __forceinline__ void mma8(float* d, const uint32_t* a, const uint32_t* b) {
    asm volatile(
        "mma.sync.aligned.m16n8k8.row.col.f32.tf32.tf32.f32 "
        "{%0,%1,%2,%3},{%4,%5,%6,%7},{%8,%9},{%0,%1,%2,%3};"
        : "+f"(d[0]), "+f"(d[1]), "+f"(d[2]), "+f"(d[3])
        : "r"(a[0]), "r"(a[1]), "r"(a[2]), "r"(a[3]), "r"(b[0]), "r"(b[1]));
}

static __device__ __forceinline__ float gelu_t(float x) {
    float z = 0.7978845608028654f * (x + 0.044715f * x * x * x);
    float t;
    asm("tanh.approx.f32 %0, %1;" : "=f"(t) : "f"(z));
    return 0.5f * x * (1.0f + t);
}

// ----------------------- smem geometry (float words) -----------------------
static constexpr int HS_STR = 132;
static constexpr int WS_SLOT = 32 * 132;       // 4224 floats per weight chunk
static constexpr int ROWS = 96;                // 2 nodes * 48 edges

static constexpr int OFF_WS = ROWS * HS_STR;           // 12672
static constexpr int OFF_PS = OFF_WS + 2 * WS_SLOT;    // 21120
static constexpr int OFF_SB = OFF_PS + 256;            // 21376
static constexpr int OFF_AX = OFF_SB + 640;            // 22016 (mask or rB)
static constexpr int OFF_PL = OFF_AX + 96;             // 22112
static constexpr int SM13   = (OFF_PL + 256) * 4;      // 89472 B

static constexpr int PG_ROWS = 64;
static constexpr int PG_OFF_WS = PG_ROWS * HS_STR;     // 8448
static constexpr int SMPG = (PG_OFF_WS + 2 * WS_SLOT) * 4;  // 67584 B

// warp-tile mma: MI x16 rows, NI x8 cols, 32 K per call
template <int MI, int NI>
static __device__ __forceinline__ void mma_tile(
    float (*acc)[NI][4],
    const uint32_t* __restrict__ Aw, int astr, int ak,
    const uint32_t* __restrict__ Wc, int g, int tg)
{
#pragma unroll
    for (int ks = 0; ks < 4; ks++) {
        const int kk = ak + ks * 8;
        const int kw = ks * 8;
        uint32_t a[MI][4], b[NI][2];
#pragma unroll
        for (int mi = 0; mi < MI; mi++) {
            const uint32_t* Ar = Aw + (mi * 16 + g) * astr + kk + tg;
            a[mi][0] = Ar[0];
            a[mi][1] = Ar[8 * astr];
            a[mi][2] = Ar[4];
            a[mi][3] = Ar[8 * astr + 4];
        }
#pragma unroll
        for (int ni = 0; ni < NI; ni++) {
            const uint32_t* Wr = Wc + (kw + tg) * 132 + ni * 8 + g;
            b[ni][0] = Wr[0];
            b[ni][1] = Wr[4 * 132];
        }
#pragma unroll
        for (int mi = 0; mi < MI; mi++)
#pragma unroll
            for (int ni = 0; ni < NI; ni++) mma8(acc[mi][ni], a[mi], b[ni]);
    }
}

// stage one 32-row weight chunk into slot
static __device__ __forceinline__ void stage_w32(
    float* Ws, int slot, const float* __restrict__ W, int chunk, int tid)
{
    uint32_t base = s2u(Ws) + slot * WS_SLOT * 4;
    for (int i = tid; i < 1024; i += 256) {
        int r = i >> 5, c4 = (i & 31) << 2;
        cp16(base + (r * 132 + c4) * 4, W + (chunk * 32 + r) * 128 + c4);
    }
}

// run one GEMM layer with A resident in Hs (koff 0..NC*32) and W streamed
// through 2 slots. Caller must have staged+committed chunks 0,1 and done
// cp_wait<1>() + __syncthreads(). Ends with all groups drained + synced.
template <int MI, int NI>
static __device__ __forceinline__ void run_layer(
    float (*acc)[NI][4], const uint32_t* Hu, int aRowBase,
    float* Ws, const float* __restrict__ W, int NC,
    int tid, int g, int tg, int wcol)
{
    const uint32_t* Wu = (const uint32_t*)Ws;
    for (int kc = 0; kc < NC; kc++) {
        mma_tile<MI, NI>(acc, Hu + aRowBase * HS_STR, HS_STR, kc * 32,
                         Wu + (kc & 1) * WS_SLOT + wcol, g, tg);
        __syncthreads();
        if (kc + 2 < NC) { stage_w32(Ws, kc & 1, W, kc + 2, tid); cp_commit(); }
        if (kc + 1 < NC) {
            if (kc + 2 < NC) cp_wait<1>(); else cp_wait<0>();
            __syncthreads();
        }
    }
}

// =================== pgemm: Out[8192,128] = X @ W[0:128,:] =================
__global__ __launch_bounds__(256, 2) void k_pgemm(
    const float* __restrict__ X, const float* __restrict__ W, int dstSel)
{
    extern __shared__ float sm[];
    float* Xs = sm;
    float* Ws = sm + PG_OFF_WS;
    float* Out = dstSel ? g_P3 : g_P1;

    const int tid = threadIdx.x, warp = tid >> 5, lane = tid & 31;
    const int g = lane >> 2, tg = lane & 3;
    const int wm = warp >> 2, wn = warp & 3;     // 2 x 4, tile 32x32
    const long r0g = (long)blockIdx.x * PG_ROWS;

    uint32_t uXs = s2u(Xs);
    for (int i = tid; i < PG_ROWS * 32; i += 256) {
        int r = i >> 5, c4 = (i & 31) << 2;
        cp16(uXs + (r * HS_STR + c4) * 4, X + (r0g + r) * Hc + c4);
    }
    stage_w32(Ws, 0, W, 0, tid);
    cp_commit();
    stage_w32(Ws, 1, W, 1, tid);
    cp_commit();

    float acc[2][4][4];
#pragma unroll
    for (int mi = 0; mi < 2; mi++)
#pragma unroll
        for (int ni = 0; ni < 4; ni++)
#pragma unroll
            for (int q = 0; q < 4; q++) acc[mi][ni][q] = 0.f;

    cp_wait<1>();
    __syncthreads();
    run_layer<2, 4>(acc, (const uint32_t*)Xs, wm * 32, Ws, W, 4, tid, g, tg, wn * 32);

#pragma unroll
    for (int mi = 0; mi < 2; mi++) {
        int rr = wm * 32 + mi * 16 + g;
#pragma unroll
        for (int ni = 0; ni < 4; ni++) {
            int c0 = wn * 32 + ni * 8 + 2 * tg;
            *(float2*)(Out + (r0g + rr) * Hc + c0) =
                make_float2(acc[mi][ni][0], acc[mi][ni][1]);
            *(float2*)(Out + (r0g + rr + 8) * Hc + c0) =
                make_float2(acc[mi][ni][2], acc[mi][ni][3]);
        }
    }
}

// ======================= Stage 1: node message + LN1 =======================
__global__ __launch_bounds__(256, 2) void k_stage1(
    const float* __restrict__ hV, const float* __restrict__ hE,
    const float* __restrict__ mA,
    const float* __restrict__ W1e, const float* __restrict__ b1,
    const float* __restrict__ W2,  const float* __restrict__ b2,
    const float* __restrict__ W3,  const float* __restrict__ b3,
    const float* __restrict__ lng, const float* __restrict__ lnb)
{
    extern __shared__ float sm[];
    float* Hs = sm;
    float* Ws = sm + OFF_WS;
    float* Ps = sm + OFF_PS;
    float* sb = sm + OFF_SB;
    float* smask = sm + OFF_AX;
    float* Pln = sm + OFF_PL;
    const uint32_t* Hu = (const uint32_t*)Hs;

    const int tid = threadIdx.x, warp = tid >> 5, lane = tid & 31;
    const int g = lane >> 2, tg = lane & 3;
    const int wm = warp >> 2, wn = warp & 3;     // 2 x 4, tile 48x32
    const int node0 = blockIdx.x * 2;
    const long e0 = (long)node0 * Kc;

    // prologue: hE rows -> Hs, Ps, W chunks 0/1
    uint32_t uHs = s2u(Hs);
    for (int i = tid; i < ROWS * 32; i += 256) {
        int r = i >> 5, c4 = (i & 31) << 2;
        cp16(uHs + (r * HS_STR + c4) * 4, hE + (e0 + r) * Hc + c4);
    }
    if (tid < 64) cp16(s2u(Ps) + tid * 16, g_P1 + (long)node0 * Hc + tid * 4);
    stage_w32(Ws, 0, W1e, 0, tid);
    cp_commit();
    stage_w32(Ws, 1, W1e, 1, tid);
    cp_commit();

    if (tid < 128) {
        sb[tid] = b1[tid]; sb[128 + tid] = b2[tid]; sb[256 + tid] = b3[tid];
        sb[384 + tid] = lng[tid]; sb[512 + tid] = lnb[tid];
    }
    if (tid < 96) smask[tid] = mA[e0 + tid];

    float acc[3][4][4];

    auto epi_gelu = [&](const float* bias) {
#pragma unroll
        for (int mi = 0; mi < 3; mi++) {
            int r0 = wm * 48 + mi * 16 + g;
#pragma unroll
            for (int ni = 0; ni < 4; ni++) {
                int c0 = wn * 32 + ni * 8 + 2 * tg;
                float b0 = bias[c0], b1v = bias[c0 + 1];
                *(float2*)(Hs + r0 * HS_STR + c0) =
                    make_float2(gelu_t(acc[mi][ni][0] + b0), gelu_t(acc[mi][ni][1] + b1v));
                *(float2*)(Hs + (r0 + 8) * HS_STR + c0) =
                    make_float2(gelu_t(acc[mi][ni][2] + b0), gelu_t(acc[mi][ni][3] + b1v));
            }
        }
    };

    cp_wait<1>();
    __syncthreads();

    // init acc from hoisted P1 (all rows of warp belong to node wm)
#pragma unroll
    for (int ni = 0; ni < 4; ni++) {
        int c0 = wn * 32 + ni * 8 + 2 * tg;
        float v0 = Ps[wm * 128 + c0], v1 = Ps[wm * 128 + c0 + 1];
#pragma unroll
        for (int mi = 0; mi < 3; mi++) {
            acc[mi][ni][0] = v0; acc[mi][ni][1] = v1;
            acc[mi][ni][2] = v0; acc[mi][ni][3] = v1;
        }
    }

    // layer 1: A = hE (resident), K=128
    run_layer<3, 4>(acc, Hu, wm * 48, Ws, W1e, 4, tid, g, tg, wn * 32);

    // prefetch W2 chunks 0/1 (slots free), overlap with epilogue
    stage_w32(Ws, 0, W2, 0, tid); cp_commit();
    stage_w32(Ws, 1, W2, 1, tid); cp_commit();
    epi_gelu(sb);
    cp_wait<1>();
    __syncthreads();

    // layer 2
#pragma unroll
    for (int mi = 0; mi < 3; mi++)
#pragma unroll
        for (int ni = 0; ni < 4; ni++)
#pragma unroll
            for (int q = 0; q < 4; q++) acc[mi][ni][q] = 0.f;
    run_layer<3, 4>(acc, Hu, wm * 48, Ws, W2, 4, tid, g, tg, wn * 32);

    stage_w32(Ws, 0, W3, 0, tid); cp_commit();
    stage_w32(Ws, 1, W3, 1, tid); cp_commit();
    epi_gelu(sb + 128);
    cp_wait<1>();
    __syncthreads();

    // layer 3
#pragma unroll
    for (int mi = 0; mi < 3; mi++)
#pragma unroll
        for (int ni = 0; ni < 4; ni++)
#pragma unroll
            for (int q = 0; q < 4; q++) acc[mi][ni][q] = 0.f;
    run_layer<3, 4>(acc, Hu, wm * 48, Ws, W3, 4, tid, g, tg, wn * 32);

    // epilogue: (acc + b3) * mask
#pragma unroll
    for (int mi = 0; mi < 3; mi++) {
        int r0 = wm * 48 + mi * 16 + g;
        float m0 = smask[r0], m1 = smask[r0 + 8];
#pragma unroll
        for (int ni = 0; ni < 4; ni++) {
            int c0 = wn * 32 + ni * 8 + 2 * tg;
            float b0 = sb[256 + c0], b1v = sb[256 + c0 + 1];
            *(float2*)(Hs + r0 * HS_STR + c0) =
                make_float2((acc[mi][ni][0] + b0) * m0, (acc[mi][ni][1] + b1v) * m0);
            *(float2*)(Hs + (r0 + 8) * HS_STR + c0) =
                make_float2((acc[mi][ni][2] + b0) * m1, (acc[mi][ni][3] + b1v) * m1);
        }
    }
    __syncthreads();

    // K-sum, residual, LN1 -> g_hV1
    {
        int nn = tid >> 7, c = tid & 127;
        float s = 0.f;
#pragma unroll 8
        for (int j = 0; j < 48; j++) s += Hs[(nn * 48 + j) * HS_STR + c];
        Pln[nn * 128 + c] = hV[(long)(node0 + nn) * Hc + c] + s * (1.0f / 30.0f);
    }
    __syncthreads();
    if (warp < 2) {
        int nn = warp;
        float x[4], s = 0.f, s2 = 0.f;
#pragma unroll
        for (int q = 0; q < 4; q++) {
            x[q] = Pln[nn * 128 + lane + 32 * q];
            s += x[q]; s2 += x[q] * x[q];
        }
#pragma unroll
        for (int off = 16; off; off >>= 1) {
            s  += __shfl_xor_sync(0xffffffffu, s,  off);
            s2 += __shfl_xor_sync(0xffffffffu, s2, off);
        }
        float mu  = s * (1.0f / 128.0f);
        float var = s2 * (1.0f / 128.0f) - mu * mu;
        float inv = rsqrtf(var + EPSLN);
#pragma unroll
        for (int q = 0; q < 4; q++) {
            int c = lane + 32 * q;
            g_hV1[(long)(node0 + nn) * Hc + c] =
                (x[q] - mu) * inv * sb[384 + c] + sb[512 + c];
        }
    }
}

// ======================= Stage 2: FFN + LN2 + mask_V =======================
static constexpr int SM2 = (128 * 36 + 512 * 36 + 32 * 128 + 896) * 4;

__global__ __launch_bounds__(256, 1) void k_stage2(
    const float* __restrict__ maskV,
    const float* __restrict__ Win,  const float* __restrict__ bin,
    const float* __restrict__ Wout, const float* __restrict__ bout,
    const float* __restrict__ lng,  const float* __restrict__ lnb,
    float* __restrict__ outV)
{
    extern __shared__ float smf[];
    float (*HT)[36] = reinterpret_cast<float(*)[36]>(smf);
    float (*TT)[36] = reinterpret_cast<float(*)[36]>(smf + 128 * 36);
    float* P  = smf + (128 + 512) * 36;
    float* sb = P + 32 * 128;

    const int tid = threadIdx.x, warp = tid >> 5, lane = tid & 31;
    const int node0 = blockIdx.x * 32;

    for (int i = tid; i < 512; i += 256) sb[i] = bin[i];
    for (int i = tid; i < 128; i += 256) {
        sb[512 + i] = bout[i]; sb[640 + i] = lng[i]; sb[768 + i] = lnb[i];
    }
    for (int i = tid; i < 32 * 128; i += 256) {
        int m = i >> 7, k = i & 127;
        HT[k][m] = g_hV1[(long)(node0 + m) * Hc + k];
    }
    __syncthreads();

    float a0[32], a1[32];
#pragma unroll
    for (int m = 0; m < 32; m++) { a0[m] = 0.f; a1[m] = 0.f; }
    const int j0 = tid, j1 = tid + 256;
    for (int k = 0; k < 128; k++) {
        float w0 = __ldg(&Win[k * 512 + j0]);
        float w1 = __ldg(&Win[k * 512 + j1]);
        const float4* hp = reinterpret_cast<const float4*>(&HT[k][0]);
#pragma unroll
        for (int q = 0; q < 8; q++) {
            float4 h = hp[q];
            a0[4 * q + 0] += h.x * w0; a0[4 * q + 1] += h.y * w0;
            a0[4 * q + 2] += h.z * w0; a0[4 * q + 3] += h.w * w0;
            a1[4 * q + 0] += h.x * w1; a1[4 * q + 1] += h.y * w1;
            a1[4 * q + 2] += h.z * w1; a1[4 * q + 3] += h.w * w1;
        }
    }
    float bj0 = sb[j0], bj1 = sb[j1];
#pragma unroll
    for (int q = 0; q < 8; q++) {
        float4 v0, v1;
        v0.x = gelu_t(a0[4 * q + 0] + bj0); v0.y = gelu_t(a0[4 * q + 1] + bj0);
        v0.z = gelu_t(a0[4 * q + 2] + bj0); v0.w = gelu_t(a0[4 * q + 3] + bj0);
        v1.x = gelu_t(a1[4 * q + 0] + bj1); v1.y = gelu_t(a1[4 * q + 1] + bj1);
        v1.z = gelu_t(a1[4 * q + 2] + bj1); v1.w = gelu_t(a1[4 * q + 3] + bj1);
        *reinterpret_cast<float4*>(&TT[j0][4 * q]) = v0;
        *reinterpret_cast<float4*>(&TT[j1][4 * q]) = v1;
    }
    __syncthreads();

    const int grp = tid >> 7, col = tid & 127;
    float c16[16];
#pragma unroll
    for (int m = 0; m < 16; m++) c16[m] = 0.f;
    for (int k = 0; k < 512; k++) {
        float w = __ldg(&Wout[k * 128 + col]);
        const float4* tp = reinterpret_cast<const float4*>(&TT[k][grp * 16]);
#pragma unroll
        for (int q = 0; q < 4; q++) {
            float4 t = tp[q];
            c16[4 * q + 0] += t.x * w; c16[4 * q + 1] += t.y * w;
            c16[4 * q + 2] += t.z * w; c16[4 * q + 3] += t.w * w;
        }
    }
#pragma unroll
    for (int m = 0; m < 16; m++) {
        int node = grp * 16 + m;
        P[node * 128 + col] = HT[col][node] + c16[m] + sb[512 + col];
    }
    __syncthreads();

    for (int q4 = 0; q4 < 4; q4++) {
        int node = warp * 4 + q4;
        float x[4], s = 0.f, s2 = 0.f;
#pragma unroll
        for (int q = 0; q < 4; q++) {
            x[q] = P[node * 128 + lane + 32 * q];
            s += x[q]; s2 += x[q] * x[q];
        }
#pragma unroll
        for (int off = 16; off; off >>= 1) {
            s  += __shfl_xor_sync(0xffffffffu, s,  off);
            s2 += __shfl_xor_sync(0xffffffffu, s2, off);
        }
        float mu  = s * (1.0f / 128.0f);
        float var = s2 * (1.0f / 128.0f) - mu * mu;
        float inv = rsqrtf(var + EPSLN);
        float mv  = maskV[node0 + node];
#pragma unroll
        for (int q = 0; q < 4; q++) {
            int c = lane + 32 * q;
            outV[(long)(node0 + node) * Hc + c] =
                mv * ((x[q] - mu) * inv * sb[640 + c] + sb[768 + c]);
        }
    }
}

// ======================= Stage 3: edge update + LN3 =======================
__global__ __launch_bounds__(256, 2) void k_stage3(
    const float* __restrict__ hV2, const float* __restrict__ hE,
    const int* __restrict__ Eidx,
    const float* __restrict__ W11m, const float* __restrict__ b11,
    const float* __restrict__ W12,  const float* __restrict__ b12,
    const float* __restrict__ W13,  const float* __restrict__ b13,
    const float* __restrict__ lng,  const float* __restrict__ lnb,
    float* __restrict__ outE)
{
    extern __shared__ float sm[];
    float* Hs = sm;
    float* Ws = sm + OFF_WS;
    float* Ps = sm + OFF_PS;
    float* sb = sm + OFF_SB;
    int* rB = (int*)(sm + OFF_AX);
    const uint32_t* Hu = (const uint32_t*)Hs;

    const int tid = threadIdx.x, warp = tid >> 5, lane = tid & 31;
    const int g = lane >> 2, tg = lane & 3;
    const int wm = warp >> 2, wn = warp & 3;
    const int node0 = blockIdx.x * 2;
    const long e0 = (long)node0 * Kc;

    // prologue
    uint32_t uHs = s2u(Hs);
    for (int i = tid; i < ROWS * 32; i += 256) {
        int r = i >> 5, c4 = (i & 31) << 2;
        cp16(uHs + (r * HS_STR + c4) * 4, hE + (e0 + r) * Hc + c4);
    }
    if (tid < 64) cp16(s2u(Ps) + tid * 16, g_P3 + (long)node0 * Hc + tid * 4);
    stage_w32(Ws, 0, W11m, 0, tid);
    cp_commit();
    stage_w32(Ws, 1, W11m, 1, tid);
    cp_commit();

    if (tid < 128) {
        sb[tid] = b11[tid]; sb[128 + tid] = b12[tid]; sb[256 + tid] = b13[tid];
        sb[384 + tid] = lng[tid]; sb[512 + tid] = lnb[tid];
    }
    if (tid < 96) {
        int node = node0 + tid / Kc;
        rB[tid] = ((node >> 11) << 11) + Eidx[e0 + tid];
    }

    float acc[3][4][4];

    auto epi_gelu = [&](const float* bias) {
#pragma unroll
        for (int mi = 0; mi < 3; mi++) {
            int r0 = wm * 48 + mi * 16 + g;
#pragma unroll
            for (int ni = 0; ni < 4; ni++) {
                int c0 = wn * 32 + ni * 8 + 2 * tg;
                float b0 = bias[c0], b1v = bias[c0 + 1];
                *(float2*)(Hs + r0 * HS_STR + c0) =
                    make_float2(gelu_t(acc[mi][ni][0] + b0), gelu_t(acc[mi][ni][1] + b1v));
                *(float2*)(Hs + (r0 + 8) * HS_STR + c0) =
                    make_float2(gelu_t(acc[mi][ni][2] + b0), gelu_t(acc[mi][ni][3] + b1v));
            }
        }
    };

    cp_wait<1>();
    __syncthreads();

#pragma unroll
    for (int ni = 0; ni < 4; ni++) {
        int c0 = wn * 32 + ni * 8 + 2 * tg;
        float v0 = Ps[wm * 128 + c0], v1 = Ps[wm * 128 + c0 + 1];
#pragma unroll
        for (int mi = 0; mi < 3; mi++) {
            acc[mi][ni][0] = v0; acc[mi][ni][1] = v1;
            acc[mi][ni][2] = v0; acc[mi][ni][3] = v1;
        }
    }

    // layer 1 phase A: A = hE (resident), W11m rows 0..127
    run_layer<3, 4>(acc, Hu, wm * 48, Ws, W11m, 4, tid, g, tg, wn * 32);

    // restage Hs with gathered hV2 rows, stage phase-B weight chunks
    const float* W11g = W11m + 128 * 128;   // rows for gathered part
    for (int i = tid; i < ROWS * 32; i += 256) {
        int r = i >> 5, c4 = (i & 31) << 2;
        cp16(uHs + (r * HS_STR + c4) * 4, hV2 + (long)rB[r] * Hc + c4);
    }
    stage_w32(Ws, 0, W11g, 0, tid);
    cp_commit();
    stage_w32(Ws, 1, W11g, 1, tid);
    cp_commit();
    cp_wait<1>();
    __syncthreads();

    // layer 1 phase B: A = gathered hV2
    run_layer<3, 4>(acc, Hu, wm * 48, Ws, W11g, 4, tid, g, tg, wn * 32);

    stage_w32(Ws, 0, W12, 0, tid); cp_commit();
    stage_w32(Ws, 1, W12, 1, tid); cp_commit();
    epi_gelu(sb);
    cp_wait<1>();
    __syncthreads();

    // layer 2
#pragma unroll
    for (int mi = 0; mi < 3; mi++)
#pragma unroll
        for (int ni = 0; ni < 4; ni++)
#pragma unroll
            for (int q = 0; q < 4; q++) acc[mi][ni][q] = 0.f;
    run_layer<3, 4>(acc, Hu, wm * 48, Ws, W12, 4, tid, g, tg, wn * 32);

    stage_w32(Ws, 0, W13, 0, tid); cp_commit();
    stage_w32(Ws, 1, W13, 1, tid); cp_commit();
    epi_gelu(sb + 128);
    cp_wait<1>();
    __syncthreads();

    // layer 3
#pragma unroll
    for (int mi = 0; mi < 3; mi++)
#pragma unroll
        for (int ni = 0; ni < 4; ni++)
#pragma unroll
            for (int q = 0; q < 4; q++) acc[mi][ni][q] = 0.f;
    run_layer<3, 4>(acc, Hu, wm * 48, Ws, W13, 4, tid, g, tg, wn * 32);

    // epilogue: acc + b13 -> Hs
#pragma unroll
    for (int mi = 0; mi < 3; mi++) {
        int r0 = wm * 48 + mi * 16 + g;
#pragma unroll
        for (int ni = 0; ni < 4; ni++) {
            int c0 = wn * 32 + ni * 8 + 2 * tg;
            float b0 = sb[256 + c0], b1v = sb[256 + c0 + 1];
            *(float2*)(Hs + r0 * HS_STR + c0) =
                make_float2(acc[mi][ni][0] + b0, acc[mi][ni][1] + b1v);
            *(float2*)(Hs + (r0 + 8) * HS_STR + c0) =
                make_float2(acc[mi][ni][2] + b0, acc[mi][ni][3] + b1v);
        }
    }
    __syncthreads();

    // residual + LN3 per edge row
    for (int r = warp; r < ROWS; r += 8) {
        long base = (e0 + r) * Hc;
        float x[4], s = 0.f, s2 = 0.f;
#pragma unroll
        for (int q = 0; q < 4; q++) {
            int c = lane + 32 * q;
            x[q] = Hs[r * HS_STR + c] + hE[base + c];
            s += x[q]; s2 += x[q] * x[q];
        }
#pragma unroll
        for (int off = 16; off; off >>= 1) {
            s  += __shfl_xor_sync(0xffffffffu, s,  off);
            s2 += __shfl_xor_sync(0xffffffffu, s2, off);
        }
        float mu  = s * (1.0f / 128.0f);
        float var = s2 * (1.0f / 128.0f) - mu * mu;
        float inv = rsqrtf(var + EPSLN);
#pragma unroll
        for (int q = 0; q < 4; q++) {
            int c = lane + 32 * q;
            outE[base + c] = (x[q] - mu) * inv * sb[384 + c] + sb[512 + c];
        }
    }
}

// ======================= launch =======================
extern "C" void kernel_launch(void* const* d_in, const int* in_sizes, int n_in,
                              void* d_out, int out_size)
{
    (void)in_sizes; (void)n_in; (void)out_size;
    const float* hV    = (const float*)d_in[0];
    const float* hE    = (const float*)d_in[1];
    const float* maskV = (const float*)d_in[2];
    const int*   Eidx  = (const int*)d_in[3];
    const float* mA    = (const float*)d_in[4];
    const float* W1w = (const float*)d_in[5],  *W1b = (const float*)d_in[6];
    const float* W2w = (const float*)d_in[7],  *W2b = (const float*)d_in[8];
    const float* W3w = (const float*)d_in[9],  *W3b = (const float*)d_in[10];
    const float* W11w = (const float*)d_in[11], *W11b = (const float*)d_in[12];
    const float* W12w = (const float*)d_in[13], *W12b = (const float*)d_in[14];
    const float* W13w = (const float*)d_in[15], *W13b = (const float*)d_in[16];
    const float* Winw = (const float*)d_in[17], *Winb = (const float*)d_in[18];
    const float* Woutw = (const float*)d_in[19], *Woutb = (const float*)d_in[20];
    const float* ln1g = (const float*)d_in[21], *ln1b = (const float*)d_in[22];
    const float* ln2g = (const float*)d_in[23], *ln2b = (const float*)d_in[24];
    const float* ln3g = (const float*)d_in[25], *ln3b = (const float*)d_in[26];

    float* outV = (float*)d_out;            // [8192,128]
    float* outE = outV + VOUT;              // [393216,128]

    cudaFuncSetAttribute(k_pgemm,  cudaFuncAttributeMaxDynamicSharedMemorySize, SMPG);
    cudaFuncSetAttribute(k_stage1, cudaFuncAttributeMaxDynamicSharedMemorySize, SM13);
    cudaFuncSetAttribute(k_stage2, cudaFuncAttributeMaxDynamicSharedMemorySize, SM2);
    cudaFuncSetAttribute(k_stage3, cudaFuncAttributeMaxDynamicSharedMemorySize, SM13);

    k_pgemm<<<BN / PG_ROWS, 256, SMPG>>>(hV, W1w, 0);
    k_stage1<<<BN / 2, 256, SM13>>>(hV, hE, mA, W1w + 128 * 128, W1b,
                                    W2w, W2b, W3w, W3b, ln1g, ln1b);
    k_stage2<<<BN / 32, 256, SM2>>>(maskV, Winw, Winb, Woutw, Woutb,
                                    ln2g, ln2b, outV);
    k_pgemm<<<BN / PG_ROWS, 256, SMPG>>>(outV, W11w, 1);
    k_stage3<<<BN / 2, 256, SM13>>>(outV, hE, Eidx, W11w + 128 * 128, W11b,
                                    W12w, W12b, W13w, W13b, ln3g, ln3b, outE);
}

// round 4
// speedup vs baseline: 5.2384x; 1.4077x over previous
#include <cuda_runtime.h>
#include <cstdint>
#include <math.h>

// ---------------------------------------------------------------------------
// DecLayer: B=4, N=2048, K=48, H=IN=128
// Round 4: bf16 mma.m16n8k16 (packed k-pair operands), pre-packed weights,
//          bf16-packed hE/hV/hV2, 64-K chunks, 2 CTAs/SM.
// ---------------------------------------------------------------------------

#define EPSLN 1e-5f

static constexpr int Kc = 48, Hc = 128;
static constexpr int BN = 8192;
static constexpr long ETOT = (long)BN * Kc;
static constexpr long VOUT = (long)BN * Hc;

// packed-weight segment offsets (in uint32 words; rows = K/2, cols = 128)
static constexpr int OW1 = 0;            // 128 kp rows (K=256)
static constexpr int OW2 = 16384;        // 64
static constexpr int OW3 = 24576;        // 64
static constexpr int OW11 = 32768;       // 192 (K=384)
static constexpr int OW12 = 57344;       // 64
static constexpr int OW13 = 65536;       // 64
static constexpr int WPTOT = 73728;

__device__ float g_hV1[BN * Hc];
__device__ float g_P1[BN * Hc];
__device__ float g_P3[BN * Hc];
__device__ uint32_t g_Wp[WPTOT];
__device__ uint32_t g_hEb[ETOT * 64];    // hE as bf16x2 words
__device__ uint32_t g_hVb[BN * 64];
__device__ uint32_t g_hV2b[BN * 64];

// ------------------------------ helpers -----------------------------------
static __device__ __forceinline__ uint32_t s2u(const void* p) {
    return (uint32_t)__cvta_generic_to_shared(p);
}
static __device__ __forceinline__ void cp16(uint32_t s, const void* g) {
    asm volatile("cp.async.cg.shared.global [%0], [%1], 16;" :: "r"(s), "l"(g));
}
static __device__ __forceinline__ void cp_commit() {
    asm volatile("cp.async.commit_group;");
}
template <int N>
static __device__ __forceinline__ void cp_wait() {
    asm volatile("cp.async.wait_group %0;" :: "n"(N));
}

static __device__ __forceinline__ uint32_t packbf(float lo, float hi) {
    uint32_t r;
    asm("cvt.rn.bf16x2.f32 %0, %1, %2;" : "=r"(r) : "f"(hi), "f"(lo));
    return r;
}

static __device__ __forceinline__ void mma16(float* d, const uint32_t* a, const uint32_t* b) {
    asm volatile(
        "mma.sync.aligned.m16n8k16.row.col.f32.bf16.bf16.f32 "
        "{%0,%1,%2,%3},{%4,%5,%6,%7},{%8,%9},{%0,%1,%2,%3};"
        : "+f"(d[0]), "+f"(d[1]), "+f"(d[2]), "+f"(d[3])
        : "r"(a[0]), "r"(a[1]), "r"(a[2]), "r"(a[3]), "r"(b[0]), "r"(b[1]));
}

static __device__ __forceinline__ float gelu_t(float x) {
    float z = 0.7978845608028654f * (x + 0.044715f * x * x * x);
    float t;
    asm("tanh.approx.f32 %0, %1;" : "=f"(t) : "f"(z));
    return 0.5f * x * (1.0f + t);
}

// ----------------------- smem geometry (32-bit words) ----------------------
static constexpr int HS_F32_STR = 132;     // fp32 final-layer view
static constexpr int HS_STR = 68;          // packed bf16x2 view (64 + 4 pad)
static constexpr int WS_STR = 136;
static constexpr int WSLOT = 32 * WS_STR;  // 4352 (32 kp rows x 128 cols)
static constexpr int ROWS = 96;

static constexpr int OFF_WS = ROWS * HS_F32_STR;       // 12672
static constexpr int OFF_PS = OFF_WS + 2 * WSLOT;      // 21376
static constexpr int OFF_SB = OFF_PS + 256;            // 21632
static constexpr int OFF_AX = OFF_SB + 640;            // 22272
static constexpr int OFF_PL = OFF_AX + 96;             // 22368
static constexpr int SM13 = (OFF_PL + 256) * 4;        // 90496 B

static constexpr int PG_ROWS = 64;
static constexpr int PG_OFF_WS = PG_ROWS * HS_STR;     // 4352
static constexpr int SMPG = (PG_OFF_WS + 2 * WSLOT) * 4;  // 52224 B

// warp-tile mma over one 32-kp chunk (4 ks-steps of 8 kp = 16 K each)
template <int MI, int NI>
static __device__ __forceinline__ void mma_tile(
    float (*acc)[NI][4],
    const uint32_t* __restrict__ Aw, int astr, int ak,
    const uint32_t* __restrict__ Wc, int g, int tg)
{
#pragma unroll
    for (int ks = 0; ks < 4; ks++) {
        const int kk = ak + ks * 8;
        const int kw = ks * 8;
        uint32_t a[MI][4], b[NI][2];
#pragma unroll
        for (int mi = 0; mi < MI; mi++) {
            const uint32_t* Ar = Aw + (mi * 16 + g) * astr + kk + tg;
            a[mi][0] = Ar[0];
            a[mi][1] = Ar[8 * astr];
            a[mi][2] = Ar[4];
            a[mi][3] = Ar[8 * astr + 4];
        }
#pragma unroll
        for (int ni = 0; ni < NI; ni++) {
            const uint32_t* Wr = Wc + (kw + tg) * WS_STR + ni * 8 + g;
            b[ni][0] = Wr[0];
            b[ni][1] = Wr[4 * WS_STR];
        }
#pragma unroll
        for (int mi = 0; mi < MI; mi++)
#pragma unroll
            for (int ni = 0; ni < NI; ni++) mma16(acc[mi][ni], a[mi], b[ni]);
    }
}

// stage one 32-kp-row packed weight chunk into slot
static __device__ __forceinline__ void stage_w32(
    float* Ws, int slot, const uint32_t* __restrict__ Wp, int chunk, int tid)
{
    uint32_t base = s2u(Ws) + slot * WSLOT * 4;
    for (int i = tid; i < 1024; i += 256) {
        int r = i >> 5, c4 = (i & 31) << 2;
        cp16(base + (r * WS_STR + c4) * 4, Wp + (chunk * 32 + r) * 128 + c4);
    }
}

// ======================= weight packing ====================================
__global__ __launch_bounds__(256) void k_packW(
    const float* __restrict__ W1, const float* __restrict__ W2,
    const float* __restrict__ W3, const float* __restrict__ W11,
    const float* __restrict__ W12, const float* __restrict__ W13)
{
    int w = blockIdx.x * 256 + threadIdx.x;
    if (w >= WPTOT) return;
    const float* src; int off;
    if      (w < OW2)  { src = W1;  off = w - OW1;  }
    else if (w < OW3)  { src = W2;  off = w - OW2;  }
    else if (w < OW11) { src = W3;  off = w - OW3;  }
    else if (w < OW12) { src = W11; off = w - OW11; }
    else if (w < OW13) { src = W12; off = w - OW12; }
    else               { src = W13; off = w - OW13; }
    int kp = off >> 7, n = off & 127;
    g_Wp[w] = packbf(src[kp * 256 + n], src[kp * 256 + 128 + n]);
}

// row-packing: fp32 [*,128] -> bf16x2 words [*,64]. sel: 0=hEb 1=hVb 2=hV2b
__global__ __launch_bounds__(256) void k_packRow(
    int sel, const float4* __restrict__ src, long nquads)
{
    long t = (long)blockIdx.x * 256 + threadIdx.x;
    if (t >= nquads) return;
    uint32_t* dst = (sel == 0) ? g_hEb : (sel == 1) ? g_hVb : g_hV2b;
    float4 v = src[t];
    dst[2 * t]     = packbf(v.x, v.y);
    dst[2 * t + 1] = packbf(v.z, v.w);
}

// =================== pgemm: Out[8192,128] = Xb @ Wp[0:64kp] ================
__global__ __launch_bounds__(256, 2) void k_pgemm(int sel)
{
    extern __shared__ float sm[];
    float* Xs = sm;
    float* Ws = sm + PG_OFF_WS;
    const uint32_t* Xb = sel ? g_hV2b : g_hVb;
    const uint32_t* Wp = g_Wp + (sel ? OW11 : OW1);
    float* Out = sel ? g_P3 : g_P1;

    const int tid = threadIdx.x, warp = tid >> 5, lane = tid & 31;
    const int g = lane >> 2, tg = lane & 3;
    const int wm = warp >> 2, wn = warp & 3;     // 2 x 4, tile 32x32
    const long r0g = (long)blockIdx.x * PG_ROWS;

    uint32_t uXs = s2u(Xs);
    for (int i = tid; i < PG_ROWS * 16; i += 256) {
        int r = i >> 4, c4 = (i & 15) << 2;
        cp16(uXs + (r * HS_STR + c4) * 4, Xb + (r0g + r) * 64 + c4);
    }
    stage_w32(Ws, 0, Wp, 0, tid);
    stage_w32(Ws, 1, Wp, 1, tid);
    cp_commit();

    float acc[2][4][4];
#pragma unroll
    for (int mi = 0; mi < 2; mi++)
#pragma unroll
        for (int ni = 0; ni < 4; ni++)
#pragma unroll
            for (int q = 0; q < 4; q++) acc[mi][ni][q] = 0.f;

    cp_wait<0>();
    __syncthreads();
    const uint32_t* Xu = (const uint32_t*)Xs + wm * 32 * HS_STR;
    const uint32_t* Wu = (const uint32_t*)Ws + wn * 32;
    mma_tile<2, 4>(acc, Xu, HS_STR, 0, Wu, g, tg);
    mma_tile<2, 4>(acc, Xu, HS_STR, 32, Wu + WSLOT, g, tg);

#pragma unroll
    for (int mi = 0; mi < 2; mi++) {
        int rr = wm * 32 + mi * 16 + g;
#pragma unroll
        for (int ni = 0; ni < 4; ni++) {
            int c0 = wn * 32 + ni * 8 + 2 * tg;
            *(float2*)(Out + (r0g + rr) * Hc + c0) =
                make_float2(acc[mi][ni][0], acc[mi][ni][1]);
            *(float2*)(Out + (r0g + rr + 8) * Hc + c0) =
                make_float2(acc[mi][ni][2], acc[mi][ni][3]);
        }
    }
}

// ======================= Stage 1: node message + LN1 =======================
__global__ __launch_bounds__(256, 2) void k_stage1(
    const float* __restrict__ hV, const float* __restrict__ mA,
    const float* __restrict__ b1, const float* __restrict__ b2,
    const float* __restrict__ b3,
    const float* __restrict__ lng, const float* __restrict__ lnb)
{
    extern __shared__ float sm[];
    float* Hs = sm;
    float* Ws = sm + OFF_WS;
    float* Ps = sm + OFF_PS;
    float* sb = sm + OFF_SB;
    float* smask = sm + OFF_AX;
    float* Pln = sm + OFF_PL;
    uint32_t* Hp = (uint32_t*)Hs;

    const int tid = threadIdx.x, warp = tid >> 5, lane = tid & 31;
    const int g = lane >> 2, tg = lane & 3;
    const int wm = warp >> 2, wn = warp & 3;     // 2 x 4, tile 48x32
    const int node0 = blockIdx.x * 2;
    const long e0 = (long)node0 * Kc;

    const uint32_t* W1e = g_Wp + OW1 + 64 * 128;
    const uint32_t* W2p = g_Wp + OW2;
    const uint32_t* W3p = g_Wp + OW3;

    // prologue: packed hE rows -> Hs, P1 -> Ps, W1e chunks 0/1
    uint32_t uHs = s2u(Hs);
    for (int i = tid; i < ROWS * 16; i += 256) {
        int r = i >> 4, c4 = (i & 15) << 2;
        cp16(uHs + (r * HS_STR + c4) * 4, g_hEb + (e0 + r) * 64 + c4);
    }
    if (tid < 64) cp16(s2u(Ps) + tid * 16, g_P1 + (long)node0 * Hc + tid * 4);
    stage_w32(Ws, 0, W1e, 0, tid);
    cp_commit();                                  // group A
    stage_w32(Ws, 1, W1e, 1, tid);
    cp_commit();                                  // group B

    if (tid < 128) {
        sb[tid] = b1[tid]; sb[128 + tid] = b2[tid]; sb[256 + tid] = b3[tid];
        sb[384 + tid] = lng[tid]; sb[512 + tid] = lnb[tid];
    }
    if (tid < 96) smask[tid] = mA[e0 + tid];

    float acc[3][4][4];
    const uint32_t* Wu = (const uint32_t*)Ws + wn * 32;
    const uint32_t* Au = (const uint32_t*)Hp + wm * 48 * HS_STR;

    auto layer = [&](const uint32_t* Wnext) {
        mma_tile<3, 4>(acc, Au, HS_STR, 0, Wu, g, tg);
        __syncthreads();
        if (Wnext) { stage_w32(Ws, 0, Wnext, 0, tid); cp_commit(); cp_wait<1>(); __syncthreads(); }
        mma_tile<3, 4>(acc, Au, HS_STR, 32, Wu + WSLOT, g, tg);
        __syncthreads();
        if (Wnext) { stage_w32(Ws, 1, Wnext, 1, tid); cp_commit(); }
    };
    auto epi_gelu = [&](const float* bias) {
#pragma unroll
        for (int mi = 0; mi < 3; mi++) {
            int r0 = wm * 48 + mi * 16 + g;
#pragma unroll
            for (int ni = 0; ni < 4; ni++) {
                int c0 = wn * 32 + ni * 8 + 2 * tg;
                float b0 = bias[c0], b1v = bias[c0 + 1];
                Hp[r0 * HS_STR + (c0 >> 1)] =
                    packbf(gelu_t(acc[mi][ni][0] + b0), gelu_t(acc[mi][ni][1] + b1v));
                Hp[(r0 + 8) * HS_STR + (c0 >> 1)] =
                    packbf(gelu_t(acc[mi][ni][2] + b0), gelu_t(acc[mi][ni][3] + b1v));
            }
        }
    };
    auto zero_acc = [&]() {
#pragma unroll
        for (int mi = 0; mi < 3; mi++)
#pragma unroll
            for (int ni = 0; ni < 4; ni++)
#pragma unroll
                for (int q = 0; q < 4; q++) acc[mi][ni][q] = 0.f;
    };

    cp_wait<1>();   // group A (Hs, Ps, W chunk0) done
    __syncthreads();

    // init acc from hoisted P1
#pragma unroll
    for (int ni = 0; ni < 4; ni++) {
        int c0 = wn * 32 + ni * 8 + 2 * tg;
        float v0 = Ps[wm * 128 + c0], v1 = Ps[wm * 128 + c0 + 1];
#pragma unroll
        for (int mi = 0; mi < 3; mi++) {
            acc[mi][ni][0] = v0; acc[mi][ni][1] = v1;
            acc[mi][ni][2] = v0; acc[mi][ni][3] = v1;
        }
    }

    layer(W2p);
    epi_gelu(sb);
    cp_wait<0>(); __syncthreads();

    zero_acc();
    layer(W3p);
    epi_gelu(sb + 128);
    cp_wait<0>(); __syncthreads();

    zero_acc();
    layer(nullptr);

    // final epilogue: (acc + b3) * mask -> fp32 Hs (stride 132)
#pragma unroll
    for (int mi = 0; mi < 3; mi++) {
        int r0 = wm * 48 + mi * 16 + g;
        float m0 = smask[r0], m1 = smask[r0 + 8];
#pragma unroll
        for (int ni = 0; ni < 4; ni++) {
            int c0 = wn * 32 + ni * 8 + 2 * tg;
            float b0 = sb[256 + c0], b1v = sb[256 + c0 + 1];
            *(float2*)(Hs + r0 * HS_F32_STR + c0) =
                make_float2((acc[mi][ni][0] + b0) * m0, (acc[mi][ni][1] + b1v) * m0);
            *(float2*)(Hs + (r0 + 8) * HS_F32_STR + c0) =
                make_float2((acc[mi][ni][2] + b0) * m1, (acc[mi][ni][3] + b1v) * m1);
        }
    }
    __syncthreads();

    // K-sum, residual, LN1 -> g_hV1
    {
        int nn = tid >> 7, c = tid & 127;
        float s = 0.f;
#pragma unroll 8
        for (int j = 0; j < 48; j++) s += Hs[(nn * 48 + j) * HS_F32_STR + c];
        Pln[nn * 128 + c] = hV[(long)(node0 + nn) * Hc + c] + s * (1.0f / 30.0f);
    }
    __syncthreads();
    if (warp < 2) {
        int nn = warp;
        float x[4], s = 0.f, s2 = 0.f;
#pragma unroll
        for (int q = 0; q < 4; q++) {
            x[q] = Pln[nn * 128 + lane + 32 * q];
            s += x[q]; s2 += x[q] * x[q];
        }
#pragma unroll
        for (int off = 16; off; off >>= 1) {
            s  += __shfl_xor_sync(0xffffffffu, s,  off);
            s2 += __shfl_xor_sync(0xffffffffu, s2, off);
        }
        float mu  = s * (1.0f / 128.0f);
        float var = s2 * (1.0f / 128.0f) - mu * mu;
        float inv = rsqrtf(var + EPSLN);
#pragma unroll
        for (int q = 0; q < 4; q++) {
            int c = lane + 32 * q;
            g_hV1[(long)(node0 + nn) * Hc + c] =
                (x[q] - mu) * inv * sb[384 + c] + sb[512 + c];
        }
    }
}

// ======================= Stage 2: FFN + LN2 + mask_V =======================
static constexpr int SM2 = (128 * 36 + 512 * 36 + 32 * 128 + 896) * 4;

__global__ __launch_bounds__(256, 1) void k_stage2(
    const float* __restrict__ maskV,
    const float* __restrict__ Win,  const float* __restrict__ bin,
    const float* __restrict__ Wout, const float* __restrict__ bout,
    const float* __restrict__ lng,  const float* __restrict__ lnb,
    float* __restrict__ outV)
{
    extern __shared__ float smf[];
    float (*HT)[36] = reinterpret_cast<float(*)[36]>(smf);
    float (*TT)[36] = reinterpret_cast<float(*)[36]>(smf + 128 * 36);
    float* P  = smf + (128 + 512) * 36;
    float* sb = P + 32 * 128;

    const int tid = threadIdx.x, warp = tid >> 5, lane = tid & 31;
    const int node0 = blockIdx.x * 32;

    for (int i = tid; i < 512; i += 256) sb[i] = bin[i];
    for (int i = tid; i < 128; i += 256) {
        sb[512 + i] = bout[i]; sb[640 + i] = lng[i]; sb[768 + i] = lnb[i];
    }
    for (int i = tid; i < 32 * 128; i += 256) {
        int m = i >> 7, k = i & 127;
        HT[k][m] = g_hV1[(long)(node0 + m) * Hc + k];
    }
    __syncthreads();

    float a0[32], a1[32];
#pragma unroll
    for (int m = 0; m < 32; m++) { a0[m] = 0.f; a1[m] = 0.f; }
    const int j0 = tid, j1 = tid + 256;
    for (int k = 0; k < 128; k++) {
        float w0 = __ldg(&Win[k * 512 + j0]);
        float w1 = __ldg(&Win[k * 512 + j1]);
        const float4* hp = reinterpret_cast<const float4*>(&HT[k][0]);
#pragma unroll
        for (int q = 0; q < 8; q++) {
            float4 h = hp[q];
            a0[4 * q + 0] += h.x * w0; a0[4 * q + 1] += h.y * w0;
            a0[4 * q + 2] += h.z * w0; a0[4 * q + 3] += h.w * w0;
            a1[4 * q + 0] += h.x * w1; a1[4 * q + 1] += h.y * w1;
            a1[4 * q + 2] += h.z * w1; a1[4 * q + 3] += h.w * w1;
        }
    }
    float bj0 = sb[j0], bj1 = sb[j1];
#pragma unroll
    for (int q = 0; q < 8; q++) {
        float4 v0, v1;
        v0.x = gelu_t(a0[4 * q + 0] + bj0); v0.y = gelu_t(a0[4 * q + 1] + bj0);
        v0.z = gelu_t(a0[4 * q + 2] + bj0); v0.w = gelu_t(a0[4 * q + 3] + bj0);
        v1.x = gelu_t(a1[4 * q + 0] + bj1); v1.y = gelu_t(a1[4 * q + 1] + bj1);
        v1.z = gelu_t(a1[4 * q + 2] + bj1); v1.w = gelu_t(a1[4 * q + 3] + bj1);
        *reinterpret_cast<float4*>(&TT[j0][4 * q]) = v0;
        *reinterpret_cast<float4*>(&TT[j1][4 * q]) = v1;
    }
    __syncthreads();

    const int grp = tid >> 7, col = tid & 127;
    float c16[16];
#pragma unroll
    for (int m = 0; m < 16; m++) c16[m] = 0.f;
    for (int k = 0; k < 512; k++) {
        float w = __ldg(&Wout[k * 128 + col]);
        const float4* tp = reinterpret_cast<const float4*>(&TT[k][grp * 16]);
#pragma unroll
        for (int q = 0; q < 4; q++) {
            float4 t = tp[q];
            c16[4 * q + 0] += t.x * w; c16[4 * q + 1] += t.y * w;
            c16[4 * q + 2] += t.z * w; c16[4 * q + 3] += t.w * w;
        }
    }
#pragma unroll
    for (int m = 0; m < 16; m++) {
        int node = grp * 16 + m;
        P[node * 128 + col] = HT[col][node] + c16[m] + sb[512 + col];
    }
    __syncthreads();

    for (int q4 = 0; q4 < 4; q4++) {
        int node = warp * 4 + q4;
        float x[4], s = 0.f, s2 = 0.f;
#pragma unroll
        for (int q = 0; q < 4; q++) {
            x[q] = P[node * 128 + lane + 32 * q];
            s += x[q]; s2 += x[q] * x[q];
        }
#pragma unroll
        for (int off = 16; off; off >>= 1) {
            s  += __shfl_xor_sync(0xffffffffu, s,  off);
            s2 += __shfl_xor_sync(0xffffffffu, s2, off);
        }
        float mu  = s * (1.0f / 128.0f);
        float var = s2 * (1.0f / 128.0f) - mu * mu;
        float inv = rsqrtf(var + EPSLN);
        float mv  = maskV[node0 + node];
#pragma unroll
        for (int q = 0; q < 4; q++) {
            int c = lane + 32 * q;
            outV[(long)(node0 + node) * Hc + c] =
                mv * ((x[q] - mu) * inv * sb[640 + c] + sb[768 + c]);
        }
    }
}

// ======================= Stage 3: edge update + LN3 =======================
__global__ __launch_bounds__(256, 2) void k_stage3(
    const float* __restrict__ hE,   // fp32 for residual
    const int* __restrict__ Eidx,
    const float* __restrict__ b11, const float* __restrict__ b12,
    const float* __restrict__ b13,
    const float* __restrict__ lng, const float* __restrict__ lnb,
    float* __restrict__ outE)
{
    extern __shared__ float sm[];
    float* Hs = sm;
    float* Ws = sm + OFF_WS;
    float* Ps = sm + OFF_PS;
    float* sb = sm + OFF_SB;
    int* rB = (int*)(sm + OFF_AX);
    uint32_t* Hp = (uint32_t*)Hs;

    const int tid = threadIdx.x, warp = tid >> 5, lane = tid & 31;
    const int g = lane >> 2, tg = lane & 3;
    const int wm = warp >> 2, wn = warp & 3;
    const int node0 = blockIdx.x * 2;
    const long e0 = (long)node0 * Kc;

    const uint32_t* W11e = g_Wp + OW11 + 64 * 128;
    const uint32_t* W11g = g_Wp + OW11 + 128 * 128;
    const uint32_t* W12p = g_Wp + OW12;
    const uint32_t* W13p = g_Wp + OW13;

    // prologue
    uint32_t uHs = s2u(Hs);
    for (int i = tid; i < ROWS * 16; i += 256) {
        int r = i >> 4, c4 = (i & 15) << 2;
        cp16(uHs + (r * HS_STR + c4) * 4, g_hEb + (e0 + r) * 64 + c4);
    }
    if (tid < 64) cp16(s2u(Ps) + tid * 16, g_P3 + (long)node0 * Hc + tid * 4);
    stage_w32(Ws, 0, W11e, 0, tid);
    cp_commit();
    stage_w32(Ws, 1, W11e, 1, tid);
    cp_commit();

    if (tid < 128) {
        sb[tid] = b11[tid]; sb[128 + tid] = b12[tid]; sb[256 + tid] = b13[tid];
        sb[384 + tid] = lng[tid]; sb[512 + tid] = lnb[tid];
    }
    if (tid < 96) {
        int node = node0 + tid / Kc;
        rB[tid] = ((node >> 11) << 11) + Eidx[e0 + tid];
    }

    float acc[3][4][4];
    const uint32_t* Wu = (const uint32_t*)Ws + wn * 32;
    const uint32_t* Au = (const uint32_t*)Hp + wm * 48 * HS_STR;

    auto layer = [&](const uint32_t* Wnext) {
        mma_tile<3, 4>(acc, Au, HS_STR, 0, Wu, g, tg);
        __syncthreads();
        if (Wnext) { stage_w32(Ws, 0, Wnext, 0, tid); cp_commit(); cp_wait<1>(); __syncthreads(); }
        mma_tile<3, 4>(acc, Au, HS_STR, 32, Wu + WSLOT, g, tg);
        __syncthreads();
        if (Wnext) { stage_w32(Ws, 1, Wnext, 1, tid); cp_commit(); }
    };
    auto epi_gelu = [&](const float* bias) {
#pragma unroll
        for (int mi = 0; mi < 3; mi++) {
            int r0 = wm * 48 + mi * 16 + g;
#pragma unroll
            for (int ni = 0; ni < 4; ni++) {
                int c0 = wn * 32 + ni * 8 + 2 * tg;
                float b0 = bias[c0], b1v = bias[c0 + 1];
                Hp[r0 * HS_STR + (c0 >> 1)] =
                    packbf(gelu_t(acc[mi][ni][0] + b0), gelu_t(acc[mi][ni][1] + b1v));
                Hp[(r0 + 8) * HS_STR + (c0 >> 1)] =
                    packbf(gelu_t(acc[mi][ni][2] + b0), gelu_t(acc[mi][ni][3] + b1v));
            }
        }
    };
    auto zero_acc = [&]() {
#pragma unroll
        for (int mi = 0; mi < 3; mi++)
#pragma unroll
            for (int ni = 0; ni < 4; ni++)
#pragma unroll
                for (int q = 0; q < 4; q++) acc[mi][ni][q] = 0.f;
    };

    cp_wait<1>();
    __syncthreads();

    // init acc from hoisted P3
#pragma unroll
    for (int ni = 0; ni < 4; ni++) {
        int c0 = wn * 32 + ni * 8 + 2 * tg;
        float v0 = Ps[wm * 128 + c0], v1 = Ps[wm * 128 + c0 + 1];
#pragma unroll
        for (int mi = 0; mi < 3; mi++) {
            acc[mi][ni][0] = v0; acc[mi][ni][1] = v1;
            acc[mi][ni][2] = v0; acc[mi][ni][3] = v1;
        }
    }

    // layer 1 phase A: A = hE (resident), next = W11g
    layer(W11g);

    // restage Hs with gathered hV2 packed rows
    for (int i = tid; i < ROWS * 16; i += 256) {
        int r = i >> 4, c4 = (i & 15) << 2;
        cp16(uHs + (r * HS_STR + c4) * 4, g_hV2b + (long)rB[r] * 64 + c4);
    }
    cp_commit();
    cp_wait<0>();
    __syncthreads();

    // layer 1 phase B: A = gathered hV2, next = W12
    layer(W12p);
    epi_gelu(sb);
    cp_wait<0>(); __syncthreads();

    zero_acc();
    layer(W13p);
    epi_gelu(sb + 128);
    cp_wait<0>(); __syncthreads();

    zero_acc();
    layer(nullptr);

    // final epilogue: acc + b13 -> fp32 Hs (stride 132)
#pragma unroll
    for (int mi = 0; mi < 3; mi++) {
        int r0 = wm * 48 + mi * 16 + g;
#pragma unroll
        for (int ni = 0; ni < 4; ni++) {
            int c0 = wn * 32 + ni * 8 + 2 * tg;
            float b0 = sb[256 + c0], b1v = sb[256 + c0 + 1];
            *(float2*)(Hs + r0 * HS_F32_STR + c0) =
                make_float2(acc[mi][ni][0] + b0, acc[mi][ni][1] + b1v);
            *(float2*)(Hs + (r0 + 8) * HS_F32_STR + c0) =
                make_float2(acc[mi][ni][2] + b0, acc[mi][ni][3] + b1v);
        }
    }
    __syncthreads();

    // residual + LN3 per edge row
    for (int r = warp; r < ROWS; r += 8) {
        long base = (e0 + r) * Hc;
        float x[4], s = 0.f, s2 = 0.f;
#pragma unroll
        for (int q = 0; q < 4; q++) {
            int c = lane + 32 * q;
            x[q] = Hs[r * HS_F32_STR + c] + hE[base + c];
            s += x[q]; s2 += x[q] * x[q];
        }
#pragma unroll
        for (int off = 16; off; off >>= 1) {
            s  += __shfl_xor_sync(0xffffffffu, s,  off);
            s2 += __shfl_xor_sync(0xffffffffu, s2, off);
        }
        float mu  = s * (1.0f / 128.0f);
        float var = s2 * (1.0f / 128.0f) - mu * mu;
        float inv = rsqrtf(var + EPSLN);
#pragma unroll
        for (int q = 0; q < 4; q++) {
            int c = lane + 32 * q;
            outE[base + c] = (x[q] - mu) * inv * sb[384 + c] + sb[512 + c];
        }
    }
}

// ======================= launch =======================
extern "C" void kernel_launch(void* const* d_in, const int* in_sizes, int n_in,
                              void* d_out, int out_size)
{
    (void)in_sizes; (void)n_in; (void)out_size;
    const float* hV    = (const float*)d_in[0];
    const float* hE    = (const float*)d_in[1];
    const float* maskV = (const float*)d_in[2];
    const int*   Eidx  = (const int*)d_in[3];
    const float* mA    = (const float*)d_in[4];
    const float* W1w = (const float*)d_in[5],  *W1b = (const float*)d_in[6];
    const float* W2w = (const float*)d_in[7],  *W2b = (const float*)d_in[8];
    const float* W3w = (const float*)d_in[9],  *W3b = (const float*)d_in[10];
    const float* W11w = (const float*)d_in[11], *W11b = (const float*)d_in[12];
    const float* W12w = (const float*)d_in[13], *W12b = (const float*)d_in[14];
    const float* W13w = (const float*)d_in[15], *W13b = (const float*)d_in[16];
    const float* Winw = (const float*)d_in[17], *Winb = (const float*)d_in[18];
    const float* Woutw = (const float*)d_in[19], *Woutb = (const float*)d_in[20];
    const float* ln1g = (const float*)d_in[21], *ln1b = (const float*)d_in[22];
    const float* ln2g = (const float*)d_in[23], *ln2b = (const float*)d_in[24];
    const float* ln3g = (const float*)d_in[25], *ln3b = (const float*)d_in[26];

    float* outV = (float*)d_out;
    float* outE = outV + VOUT;

    cudaFuncSetAttribute(k_pgemm,  cudaFuncAttributeMaxDynamicSharedMemorySize, SMPG);
    cudaFuncSetAttribute(k_stage1, cudaFuncAttributeMaxDynamicSharedMemorySize, SM13);
    cudaFuncSetAttribute(k_stage2, cudaFuncAttributeMaxDynamicSharedMemorySize, SM2);
    cudaFuncSetAttribute(k_stage3, cudaFuncAttributeMaxDynamicSharedMemorySize, SM13);

    k_packW<<<(WPTOT + 255) / 256, 256>>>(W1w, W2w, W3w, W11w, W12w, W13w);
    k_packRow<<<49152, 256>>>(0, (const float4*)hE, (long)ETOT * 32);
    k_packRow<<<1024, 256>>>(1, (const float4*)hV, (long)BN * 32);
    k_pgemm<<<BN / PG_ROWS, 256, SMPG>>>(0);
    k_stage1<<<BN / 2, 256, SM13>>>(hV, mA, W1b, W2b, W3b, ln1g, ln1b);
    k_stage2<<<BN / 32, 256, SM2>>>(maskV, Winw, Winb, Woutw, Woutb,
                                    ln2g, ln2b, outV);
    k_packRow<<<1024, 256>>>(2, (const float4*)outV, (long)BN * 32);
    k_pgemm<<<BN / PG_ROWS, 256, SMPG>>>(1);
    k_stage3<<<BN / 2, 256, SM13>>>(hE, Eidx, W11b, W12b, W13b,
                                    ln3g, ln3b, outE);
}

// round 7
// speedup vs baseline: 5.2405x; 1.0004x over previous
#include <cuda_runtime.h>
#include <cstdint>
#include <math.h>

// ---------------------------------------------------------------------------
// DecLayer: B=4, N=2048, K=48, H=IN=128
// Round 7: round-4 passing base + ONE delta: A-operand via ldmatrix.x4.
//          (B stays scalar-LDS from k-major packed weights, as in round 4.)
// ---------------------------------------------------------------------------

#define EPSLN 1e-5f

static constexpr int Kc = 48, Hc = 128;
static constexpr int BN = 8192;
static constexpr long ETOT = (long)BN * Kc;
static constexpr long VOUT = (long)BN * Hc;

// packed-weight segment offsets (in uint32 words; rows = K/2, cols = 128)
static constexpr int OW1 = 0;            // 128 kp rows (K=256)
static constexpr int OW2 = 16384;        // 64
static constexpr int OW3 = 24576;        // 64
static constexpr int OW11 = 32768;       // 192 (K=384)
static constexpr int OW12 = 57344;       // 64
static constexpr int OW13 = 65536;       // 64
static constexpr int WPTOT = 73728;

__device__ float g_hV1[BN * Hc];
__device__ float g_P1[BN * Hc];
__device__ float g_P3[BN * Hc];
__device__ uint32_t g_Wp[WPTOT];
__device__ uint32_t g_hEb[ETOT * 64];    // hE as bf16x2 words
__device__ uint32_t g_hVb[BN * 64];
__device__ uint32_t g_hV2b[BN * 64];

// ------------------------------ helpers -----------------------------------
static __device__ __forceinline__ uint32_t s2u(const void* p) {
    return (uint32_t)__cvta_generic_to_shared(p);
}
static __device__ __forceinline__ void cp16(uint32_t s, const void* g) {
    asm volatile("cp.async.cg.shared.global [%0], [%1], 16;" :: "r"(s), "l"(g));
}
static __device__ __forceinline__ void cp_commit() {
    asm volatile("cp.async.commit_group;");
}
template <int N>
static __device__ __forceinline__ void cp_wait() {
    asm volatile("cp.async.wait_group %0;" :: "n"(N));
}

static __device__ __forceinline__ uint32_t packbf(float lo, float hi) {
    uint32_t r;
    asm("cvt.rn.bf16x2.f32 %0, %1, %2;" : "=r"(r) : "f"(hi), "f"(lo));
    return r;
}

static __device__ __forceinline__ void ldsm4(uint32_t* r, uint32_t saddr) {
    asm volatile("ldmatrix.sync.aligned.m8n8.x4.shared.b16 {%0,%1,%2,%3}, [%4];"
        : "=r"(r[0]), "=r"(r[1]), "=r"(r[2]), "=r"(r[3]) : "r"(saddr));
}

static __device__ __forceinline__ void mma16(float* d, const uint32_t* a, const uint32_t* b) {
    asm volatile(
        "mma.sync.aligned.m16n8k16.row.col.f32.bf16.bf16.f32 "
        "{%0,%1,%2,%3},{%4,%5,%6,%7},{%8,%9},{%0,%1,%2,%3};"
        : "+f"(d[0]), "+f"(d[1]), "+f"(d[2]), "+f"(d[3])
        : "r"(a[0]), "r"(a[1]), "r"(a[2]), "r"(a[3]), "r"(b[0]), "r"(b[1]));
}

static __device__ __forceinline__ float gelu_t(float x) {
    float z = 0.7978845608028654f * (x + 0.044715f * x * x * x);
    float t;
    asm("tanh.approx.f32 %0, %1;" : "=f"(t) : "f"(z));
    return 0.5f * x * (1.0f + t);
}

// ----------------------- smem geometry (32-bit words) ----------------------
static constexpr int HS_F32_STR = 132;     // fp32 final-layer view
static constexpr int HS_STR = 68;          // packed bf16x2 view (64 + 4 pad)
static constexpr int WS_STR = 136;
static constexpr int WSLOT = 32 * WS_STR;  // 4352 (32 kp rows x 128 cols)
static constexpr int ROWS = 96;

static constexpr int OFF_WS = ROWS * HS_F32_STR;       // 12672
static constexpr int OFF_PS = OFF_WS + 2 * WSLOT;      // 21376
static constexpr int OFF_SB = OFF_PS + 256;            // 21632
static constexpr int OFF_AX = OFF_SB + 640;            // 22272
static constexpr int OFF_PL = OFF_AX + 96;             // 22368
static constexpr int SM13 = (OFF_PL + 256) * 4;        // 90496 B

static constexpr int PG_ROWS = 64;
static constexpr int PG_OFF_WS = PG_ROWS * HS_STR;     // 4352
static constexpr int SMPG = (PG_OFF_WS + 2 * WSLOT) * 4;  // 52224 B

// per-lane ldmatrix address offsets (A operand, non-transposed)
static __device__ __forceinline__ int a_row(int lane) {
    return (lane & 7) + ((lane >> 3) & 1) * 8;
}
static __device__ __forceinline__ int a_col(int lane) { return (lane >> 4) * 4; }

// warp-tile mma over one 32-kp chunk: A via ldmatrix.x4, B via scalar LDS
// (register contents identical to the round-4 all-LDS version).
template <int MI>
static __device__ __forceinline__ void mma_tile(
    float (*acc)[4][4],
    uint32_t aBase, int astr, int ak,                  // smem byte addr of A frag
    const uint32_t* __restrict__ Wc,                   // k-major weight slot
    int g, int tg)
{
#pragma unroll
    for (int ks = 0; ks < 4; ks++) {
        const int kw = ks * 8;
        uint32_t a[MI][4], b[4][2];
#pragma unroll
        for (int mi = 0; mi < MI; mi++)
            ldsm4(a[mi], aBase + (mi * 16 * astr + ak + kw) * 4);
#pragma unroll
        for (int ni = 0; ni < 4; ni++) {
            const uint32_t* Wr = Wc + (kw + tg) * WS_STR + ni * 8 + g;
            b[ni][0] = Wr[0];
            b[ni][1] = Wr[4 * WS_STR];
        }
#pragma unroll
        for (int mi = 0; mi < MI; mi++)
#pragma unroll
            for (int ni = 0; ni < 4; ni++) mma16(acc[mi][ni], a[mi], b[ni]);
    }
}

// stage one 32-kp-row packed weight chunk into slot (round-4 layout)
static __device__ __forceinline__ void stage_w32(
    float* Ws, int slot, const uint32_t* __restrict__ Wp, int chunk, int tid)
{
    uint32_t base = s2u(Ws) + slot * WSLOT * 4;
    for (int i = tid; i < 1024; i += 256) {
        int r = i >> 5, c4 = (i & 31) << 2;
        cp16(base + (r * WS_STR + c4) * 4, Wp + (chunk * 32 + r) * 128 + c4);
    }
}

// ======================= weight packing (round-4 layout) ===================
__global__ __launch_bounds__(256) void k_packW(
    const float* __restrict__ W1, const float* __restrict__ W2,
    const float* __restrict__ W3, const float* __restrict__ W11,
    const float* __restrict__ W12, const float* __restrict__ W13)
{
    int w = blockIdx.x * 256 + threadIdx.x;
    if (w >= WPTOT) return;
    const float* src; int off;
    if      (w < OW2)  { src = W1;  off = w - OW1;  }
    else if (w < OW3)  { src = W2;  off = w - OW2;  }
    else if (w < OW11) { src = W3;  off = w - OW3;  }
    else if (w < OW12) { src = W11; off = w - OW11; }
    else if (w < OW13) { src = W12; off = w - OW12; }
    else               { src = W13; off = w - OW13; }
    int kp = off >> 7, n = off & 127;
    g_Wp[w] = packbf(src[kp * 256 + n], src[kp * 256 + 128 + n]);
}

// row-packing: fp32 [*,128] -> bf16x2 words [*,64]. sel: 0=hEb 1=hVb 2=hV2b
__global__ __launch_bounds__(256) void k_packRow(
    int sel, const float4* __restrict__ src, long nquads)
{
    long t = (long)blockIdx.x * 256 + threadIdx.x;
    if (t >= nquads) return;
    uint32_t* dst = (sel == 0) ? g_hEb : (sel == 1) ? g_hVb : g_hV2b;
    float4 v = src[t];
    dst[2 * t]     = packbf(v.x, v.y);
    dst[2 * t + 1] = packbf(v.z, v.w);
}

// =================== pgemm: Out[8192,128] = Xb @ Wp[0:64kp] ================
__global__ __launch_bounds__(256, 2) void k_pgemm(int sel)
{
    extern __shared__ float sm[];
    float* Xs = sm;
    float* Ws = sm + PG_OFF_WS;
    const uint32_t* Xb = sel ? g_hV2b : g_hVb;
    const uint32_t* Wp = g_Wp + (sel ? OW11 : OW1);
    float* Out = sel ? g_P3 : g_P1;

    const int tid = threadIdx.x, warp = tid >> 5, lane = tid & 31;
    const int g = lane >> 2, tg = lane & 3;
    const int wm = warp >> 2, wn = warp & 3;     // 2 x 4, tile 32x32
    const long r0g = (long)blockIdx.x * PG_ROWS;

    uint32_t uXs = s2u(Xs);
    for (int i = tid; i < PG_ROWS * 16; i += 256) {
        int r = i >> 4, c4 = (i & 15) << 2;
        cp16(uXs + (r * HS_STR + c4) * 4, Xb + (r0g + r) * 64 + c4);
    }
    stage_w32(Ws, 0, Wp, 0, tid);
    stage_w32(Ws, 1, Wp, 1, tid);
    cp_commit();

    float acc[2][4][4];
#pragma unroll
    for (int mi = 0; mi < 2; mi++)
#pragma unroll
        for (int ni = 0; ni < 4; ni++)
#pragma unroll
            for (int q = 0; q < 4; q++) acc[mi][ni][q] = 0.f;

    const uint32_t aBase = uXs + ((wm * 32 + a_row(lane)) * HS_STR + a_col(lane)) * 4;
    const uint32_t* Wu = (const uint32_t*)Ws + wn * 32;

    cp_wait<0>();
    __syncthreads();
    mma_tile<2>(acc, aBase, HS_STR, 0, Wu, g, tg);
    mma_tile<2>(acc, aBase, HS_STR, 32, Wu + WSLOT, g, tg);

#pragma unroll
    for (int mi = 0; mi < 2; mi++) {
        int rr = wm * 32 + mi * 16 + g;
#pragma unroll
        for (int ni = 0; ni < 4; ni++) {
            int c0v = wn * 32 + ni * 8 + 2 * tg;
            *(float2*)(Out + (r0g + rr) * Hc + c0v) =
                make_float2(acc[mi][ni][0], acc[mi][ni][1]);
            *(float2*)(Out + (r0g + rr + 8) * Hc + c0v) =
                make_float2(acc[mi][ni][2], acc[mi][ni][3]);
        }
    }
}

// ======================= Stage 1: node message + LN1 =======================
__global__ __launch_bounds__(256, 2) void k_stage1(
    const float* __restrict__ hV, const float* __restrict__ mA,
    const float* __restrict__ b1, const float* __restrict__ b2,
    const float* __restrict__ b3,
    const float* __restrict__ lng, const float* __restrict__ lnb)
{
    extern __shared__ float sm[];
    float* Hs = sm;
    float* Ws = sm + OFF_WS;
    float* Ps = sm + OFF_PS;
    float* sb = sm + OFF_SB;
    float* smask = sm + OFF_AX;
    float* Pln = sm + OFF_PL;
    uint32_t* Hp = (uint32_t*)Hs;

    const int tid = threadIdx.x, warp = tid >> 5, lane = tid & 31;
    const int g = lane >> 2, tg = lane & 3;
    const int wm = warp >> 2, wn = warp & 3;     // 2 x 4, tile 48x32
    const int node0 = blockIdx.x * 2;
    const long e0 = (long)node0 * Kc;

    const uint32_t* W1e = g_Wp + OW1 + 64 * 128;
    const uint32_t* W2p = g_Wp + OW2;
    const uint32_t* W3p = g_Wp + OW3;

    // prologue: packed hE rows -> Hs, P1 -> Ps, W1e chunks 0/1
    uint32_t uHs = s2u(Hs);
    for (int i = tid; i < ROWS * 16; i += 256) {
        int r = i >> 4, c4 = (i & 15) << 2;
        cp16(uHs + (r * HS_STR + c4) * 4, g_hEb + (e0 + r) * 64 + c4);
    }
    if (tid < 64) cp16(s2u(Ps) + tid * 16, g_P1 + (long)node0 * Hc + tid * 4);
    stage_w32(Ws, 0, W1e, 0, tid);
    cp_commit();                                  // group A
    stage_w32(Ws, 1, W1e, 1, tid);
    cp_commit();                                  // group B

    if (tid < 128) {
        sb[tid] = b1[tid]; sb[128 + tid] = b2[tid]; sb[256 + tid] = b3[tid];
        sb[384 + tid] = lng[tid]; sb[512 + tid] = lnb[tid];
    }
    if (tid < 96) smask[tid] = mA[e0 + tid];

    float acc[3][4][4];
    const uint32_t aBase = uHs + ((wm * 48 + a_row(lane)) * HS_STR + a_col(lane)) * 4;
    const uint32_t* Wu = (const uint32_t*)Ws + wn * 32;

    auto layer = [&](const uint32_t* Wnext) {
        mma_tile<3>(acc, aBase, HS_STR, 0, Wu, g, tg);
        __syncthreads();
        if (Wnext) { stage_w32(Ws, 0, Wnext, 0, tid); cp_commit(); cp_wait<1>(); __syncthreads(); }
        mma_tile<3>(acc, aBase, HS_STR, 32, Wu + WSLOT, g, tg);
        __syncthreads();
        if (Wnext) { stage_w32(Ws, 1, Wnext, 1, tid); cp_commit(); }
    };
    auto epi_gelu = [&](const float* bias) {
#pragma unroll
        for (int mi = 0; mi < 3; mi++) {
            int r0 = wm * 48 + mi * 16 + g;
#pragma unroll
            for (int ni = 0; ni < 4; ni++) {
                int c0 = wn * 32 + ni * 8 + 2 * tg;
                float b0 = bias[c0], b1v = bias[c0 + 1];
                Hp[r0 * HS_STR + (c0 >> 1)] =
                    packbf(gelu_t(acc[mi][ni][0] + b0), gelu_t(acc[mi][ni][1] + b1v));
                Hp[(r0 + 8) * HS_STR + (c0 >> 1)] =
                    packbf(gelu_t(acc[mi][ni][2] + b0), gelu_t(acc[mi][ni][3] + b1v));
            }
        }
    };
    auto zero_acc = [&]() {
#pragma unroll
        for (int mi = 0; mi < 3; mi++)
#pragma unroll
            for (int ni = 0; ni < 4; ni++)
#pragma unroll
                for (int q = 0; q < 4; q++) acc[mi][ni][q] = 0.f;
    };

    cp_wait<1>();   // group A (Hs, Ps, W chunk0) done
    __syncthreads();

    // init acc from hoisted P1
#pragma unroll
    for (int ni = 0; ni < 4; ni++) {
        int c0 = wn * 32 + ni * 8 + 2 * tg;
        float v0 = Ps[wm * 128 + c0], v1 = Ps[wm * 128 + c0 + 1];
#pragma unroll
        for (int mi = 0; mi < 3; mi++) {
            acc[mi][ni][0] = v0; acc[mi][ni][1] = v1;
            acc[mi][ni][2] = v0; acc[mi][ni][3] = v1;
        }
    }

    layer(W2p);
    epi_gelu(sb);
    cp_wait<0>(); __syncthreads();

    zero_acc();
    layer(W3p);
    epi_gelu(sb + 128);
    cp_wait<0>(); __syncthreads();

    zero_acc();
    layer(nullptr);

    // final epilogue: (acc + b3) * mask -> fp32 Hs (stride 132)
#pragma unroll
    for (int mi = 0; mi < 3; mi++) {
        int r0 = wm * 48 + mi * 16 + g;
        float m0 = smask[r0], m1 = smask[r0 + 8];
#pragma unroll
        for (int ni = 0; ni < 4; ni++) {
            int c0 = wn * 32 + ni * 8 + 2 * tg;
            float b0 = sb[256 + c0], b1v = sb[256 + c0 + 1];
            *(float2*)(Hs + r0 * HS_F32_STR + c0) =
                make_float2((acc[mi][ni][0] + b0) * m0, (acc[mi][ni][1] + b1v) * m0);
            *(float2*)(Hs + (r0 + 8) * HS_F32_STR + c0) =
                make_float2((acc[mi][ni][2] + b0) * m1, (acc[mi][ni][3] + b1v) * m1);
        }
    }
    __syncthreads();

    // K-sum, residual, LN1 -> g_hV1
    {
        int nn = tid >> 7, c = tid & 127;
        float s = 0.f;
#pragma unroll 8
        for (int j = 0; j < 48; j++) s += Hs[(nn * 48 + j) * HS_F32_STR + c];
        Pln[nn * 128 + c] = hV[(long)(node0 + nn) * Hc + c] + s * (1.0f / 30.0f);
    }
    __syncthreads();
    if (warp < 2) {
        int nn = warp;
        float x[4], s = 0.f, s2 = 0.f;
#pragma unroll
        for (int q = 0; q < 4; q++) {
            x[q] = Pln[nn * 128 + lane + 32 * q];
            s += x[q]; s2 += x[q] * x[q];
        }
#pragma unroll
        for (int off = 16; off; off >>= 1) {
            s  += __shfl_xor_sync(0xffffffffu, s,  off);
            s2 += __shfl_xor_sync(0xffffffffu, s2, off);
        }
        float mu  = s * (1.0f / 128.0f);
        float var = s2 * (1.0f / 128.0f) - mu * mu;
        float inv = rsqrtf(var + EPSLN);
#pragma unroll
        for (int q = 0; q < 4; q++) {
            int c = lane + 32 * q;
            g_hV1[(long)(node0 + nn) * Hc + c] =
                (x[q] - mu) * inv * sb[384 + c] + sb[512 + c];
        }
    }
}

// ======================= Stage 2: FFN + LN2 + mask_V =======================
static constexpr int SM2 = (128 * 36 + 512 * 36 + 32 * 128 + 896) * 4;

__global__ __launch_bounds__(256, 1) void k_stage2(
    const float* __restrict__ maskV,
    const float* __restrict__ Win,  const float* __restrict__ bin,
    const float* __restrict__ Wout, const float* __restrict__ bout,
    const float* __restrict__ lng,  const float* __restrict__ lnb,
    float* __restrict__ outV)
{
    extern __shared__ float smf[];
    float (*HT)[36] = reinterpret_cast<float(*)[36]>(smf);
    float (*TT)[36] = reinterpret_cast<float(*)[36]>(smf + 128 * 36);
    float* P  = smf + (128 + 512) * 36;
    float* sb = P + 32 * 128;

    const int tid = threadIdx.x, warp = tid >> 5, lane = tid & 31;
    const int node0 = blockIdx.x * 32;

    for (int i = tid; i < 512; i += 256) sb[i] = bin[i];
    for (int i = tid; i < 128; i += 256) {
        sb[512 + i] = bout[i]; sb[640 + i] = lng[i]; sb[768 + i] = lnb[i];
    }
    for (int i = tid; i < 32 * 128; i += 256) {
        int m = i >> 7, k = i & 127;
        HT[k][m] = g_hV1[(long)(node0 + m) * Hc + k];
    }
    __syncthreads();

    float a0[32], a1[32];
#pragma unroll
    for (int m = 0; m < 32; m++) { a0[m] = 0.f; a1[m] = 0.f; }
    const int j0 = tid, j1 = tid + 256;
    for (int k = 0; k < 128; k++) {
        float w0 = __ldg(&Win[k * 512 + j0]);
        float w1 = __ldg(&Win[k * 512 + j1]);
        const float4* hp = reinterpret_cast<const float4*>(&HT[k][0]);
#pragma unroll
        for (int q = 0; q < 8; q++) {
            float4 h = hp[q];
            a0[4 * q + 0] += h.x * w0; a0[4 * q + 1] += h.y * w0;
            a0[4 * q + 2] += h.z * w0; a0[4 * q + 3] += h.w * w0;
            a1[4 * q + 0] += h.x * w1; a1[4 * q + 1] += h.y * w1;
            a1[4 * q + 2] += h.z * w1; a1[4 * q + 3] += h.w * w1;
        }
    }
    float bj0 = sb[j0], bj1 = sb[j1];
#pragma unroll
    for (int q = 0; q < 8; q++) {
        float4 v0, v1;
        v0.x = gelu_t(a0[4 * q + 0] + bj0); v0.y = gelu_t(a0[4 * q + 1] + bj0);
        v0.z = gelu_t(a0[4 * q + 2] + bj0); v0.w = gelu_t(a0[4 * q + 3] + bj0);
        v1.x = gelu_t(a1[4 * q + 0] + bj1); v1.y = gelu_t(a1[4 * q + 1] + bj1);
        v1.z = gelu_t(a1[4 * q + 2] + bj1); v1.w = gelu_t(a1[4 * q + 3] + bj1);
        *reinterpret_cast<float4*>(&TT[j0][4 * q]) = v0;
        *reinterpret_cast<float4*>(&TT[j1][4 * q]) = v1;
    }
    __syncthreads();

    const int grp = tid >> 7, col = tid & 127;
    float c16[16];
#pragma unroll
    for (int m = 0; m < 16; m++) c16[m] = 0.f;
    for (int k = 0; k < 512; k++) {
        float w = __ldg(&Wout[k * 128 + col]);
        const float4* tp = reinterpret_cast<const float4*>(&TT[k][grp * 16]);
#pragma unroll
        for (int q = 0; q < 4; q++) {
            float4 t = tp[q];
            c16[4 * q + 0] += t.x * w; c16[4 * q + 1] += t.y * w;
            c16[4 * q + 2] += t.z * w; c16[4 * q + 3] += t.w * w;
        }
    }
#pragma unroll
    for (int m = 0; m < 16; m++) {
        int node = grp * 16 + m;
        P[node * 128 + col] = HT[col][node] + c16[m] + sb[512 + col];
    }
    __syncthreads();

    for (int q4 = 0; q4 < 4; q4++) {
        int node = warp * 4 + q4;
        float x[4], s = 0.f, s2 = 0.f;
#pragma unroll
        for (int q = 0; q < 4; q++) {
            x[q] = P[node * 128 + lane + 32 * q];
            s += x[q]; s2 += x[q] * x[q];
        }
#pragma unroll
        for (int off = 16; off; off >>= 1) {
            s  += __shfl_xor_sync(0xffffffffu, s,  off);
            s2 += __shfl_xor_sync(0xffffffffu, s2, off);
        }
        float mu  = s * (1.0f / 128.0f);
        float var = s2 * (1.0f / 128.0f) - mu * mu;
        float inv = rsqrtf(var + EPSLN);
        float mv  = maskV[node0 + node];
#pragma unroll
        for (int q = 0; q < 4; q++) {
            int c = lane + 32 * q;
            outV[(long)(node0 + node) * Hc + c] =
                mv * ((x[q] - mu) * inv * sb[640 + c] + sb[768 + c]);
        }
    }
}

// ======================= Stage 3: edge update + LN3 =======================
__global__ __launch_bounds__(256, 2) void k_stage3(
    const float* __restrict__ hE,   // fp32 for residual
    const int* __restrict__ Eidx,
    const float* __restrict__ b11, const float* __restrict__ b12,
    const float* __restrict__ b13,
    const float* __restrict__ lng, const float* __restrict__ lnb,
    float* __restrict__ outE)
{
    extern __shared__ float sm[];
    float* Hs = sm;
    float* Ws = sm + OFF_WS;
    float* Ps = sm + OFF_PS;
    float* sb = sm + OFF_SB;
    int* rB = (int*)(sm + OFF_AX);
    uint32_t* Hp = (uint32_t*)Hs;

    const int tid = threadIdx.x, warp = tid >> 5, lane = tid & 31;
    const int g = lane >> 2, tg = lane & 3;
    const int wm = warp >> 2, wn = warp & 3;
    const int node0 = blockIdx.x * 2;
    const long e0 = (long)node0 * Kc;

    const uint32_t* W11e = g_Wp + OW11 + 64 * 128;
    const uint32_t* W11g = g_Wp + OW11 + 128 * 128;
    const uint32_t* W12p = g_Wp + OW12;
    const uint32_t* W13p = g_Wp + OW13;

    // prologue
    uint32_t uHs = s2u(Hs);
    for (int i = tid; i < ROWS * 16; i += 256) {
        int r = i >> 4, c4 = (i & 15) << 2;
        cp16(uHs + (r * HS_STR + c4) * 4, g_hEb + (e0 + r) * 64 + c4);
    }
    if (tid < 64) cp16(s2u(Ps) + tid * 16, g_P3 + (long)node0 * Hc + tid * 4);
    stage_w32(Ws, 0, W11e, 0, tid);
    cp_commit();
    stage_w32(Ws, 1, W11e, 1, tid);
    cp_commit();

    if (tid < 128) {
        sb[tid] = b11[tid]; sb[128 + tid] = b12[tid]; sb[256 + tid] = b13[tid];
        sb[384 + tid] = lng[tid]; sb[512 + tid] = lnb[tid];
    }
    if (tid < 96) {
        int node = node0 + tid / Kc;
        rB[tid] = ((node >> 11) << 11) + Eidx[e0 + tid];
    }

    float acc[3][4][4];
    const uint32_t aBase = uHs + ((wm * 48 + a_row(lane)) * HS_STR + a_col(lane)) * 4;
    const uint32_t* Wu = (const uint32_t*)Ws + wn * 32;

    auto layer = [&](const uint32_t* Wnext) {
        mma_tile<3>(acc, aBase, HS_STR, 0, Wu, g, tg);
        __syncthreads();
        if (Wnext) { stage_w32(Ws, 0, Wnext, 0, tid); cp_commit(); cp_wait<1>(); __syncthreads(); }
        mma_tile<3>(acc, aBase, HS_STR, 32, Wu + WSLOT, g, tg);
        __syncthreads();
        if (Wnext) { stage_w32(Ws, 1, Wnext, 1, tid); cp_commit(); }
    };
    auto epi_gelu = [&](const float* bias) {
#pragma unroll
        for (int mi = 0; mi < 3; mi++) {
            int r0 = wm * 48 + mi * 16 + g;
#pragma unroll
            for (int ni = 0; ni < 4; ni++) {
                int c0 = wn * 32 + ni * 8 + 2 * tg;
                float b0 = bias[c0], b1v = bias[c0 + 1];
                Hp[r0 * HS_STR + (c0 >> 1)] =
                    packbf(gelu_t(acc[mi][ni][0] + b0), gelu_t(acc[mi][ni][1] + b1v));
                Hp[(r0 + 8) * HS_STR + (c0 >> 1)] =
                    packbf(gelu_t(acc[mi][ni][2] + b0), gelu_t(acc[mi][ni][3] + b1v));
            }
        }
    };
    auto zero_acc = [&]() {
#pragma unroll
        for (int mi = 0; mi < 3; mi++)
#pragma unroll
            for (int ni = 0; ni < 4; ni++)
#pragma unroll
                for (int q = 0; q < 4; q++) acc[mi][ni][q] = 0.f;
    };

    cp_wait<1>();
    __syncthreads();

    // init acc from hoisted P3
#pragma unroll
    for (int ni = 0; ni < 4; ni++) {
        int c0 = wn * 32 + ni * 8 + 2 * tg;
        float v0 = Ps[wm * 128 + c0], v1 = Ps[wm * 128 + c0 + 1];
#pragma unroll
        for (int mi = 0; mi < 3; mi++) {
            acc[mi][ni][0] = v0; acc[mi][ni][1] = v1;
            acc[mi][ni][2] = v0; acc[mi][ni][3] = v1;
        }
    }

    // layer 1 phase A: A = hE (resident), next = W11g
    layer(W11g);

    // restage Hs with gathered hV2 packed rows
    for (int i = tid; i < ROWS * 16; i += 256) {
        int r = i >> 4, c4 = (i & 15) << 2;
        cp16(uHs + (r * HS_STR + c4) * 4, g_hV2b + (long)rB[r] * 64 + c4);
    }
    cp_commit();
    cp_wait<0>();
    __syncthreads();

    // layer 1 phase B: A = gathered hV2, next = W12
    layer(W12p);
    epi_gelu(sb);
    cp_wait<0>(); __syncthreads();

    zero_acc();
    layer(W13p);
    epi_gelu(sb + 128);
    cp_wait<0>(); __syncthreads();

    zero_acc();
    layer(nullptr);

    // final epilogue: acc + b13 -> fp32 Hs (stride 132)
#pragma unroll
    for (int mi = 0; mi < 3; mi++) {
        int r0 = wm * 48 + mi * 16 + g;
#pragma unroll
        for (int ni = 0; ni < 4; ni++) {
            int c0 = wn * 32 + ni * 8 + 2 * tg;
            float b0 = sb[256 + c0], b1v = sb[256 + c0 + 1];
            *(float2*)(Hs + r0 * HS_F32_STR + c0) =
                make_float2(acc[mi][ni][0] + b0, acc[mi][ni][1] + b1v);
            *(float2*)(Hs + (r0 + 8) * HS_F32_STR + c0) =
                make_float2(acc[mi][ni][2] + b0, acc[mi][ni][3] + b1v);
        }
    }
    __syncthreads();

    // residual + LN3 per edge row
    for (int r = warp; r < ROWS; r += 8) {
        long base = (e0 + r) * Hc;
        float x[4], s = 0.f, s2 = 0.f;
#pragma unroll
        for (int q = 0; q < 4; q++) {
            int c = lane + 32 * q;
            x[q] = Hs[r * HS_F32_STR + c] + hE[base + c];
            s += x[q]; s2 += x[q] * x[q];
        }
#pragma unroll
        for (int off = 16; off; off >>= 1) {
            s  += __shfl_xor_sync(0xffffffffu, s,  off);
            s2 += __shfl_xor_sync(0xffffffffu, s2, off);
        }
        float mu  = s * (1.0f / 128.0f);
        float var = s2 * (1.0f / 128.0f) - mu * mu;
        float inv = rsqrtf(var + EPSLN);
#pragma unroll
        for (int q = 0; q < 4; q++) {
            int c = lane + 32 * q;
            outE[base + c] = (x[q] - mu) * inv * sb[384 + c] + sb[512 + c];
        }
    }
}

// ======================= launch =======================
extern "C" void kernel_launch(void* const* d_in, const int* in_sizes, int n_in,
                              void* d_out, int out_size)
{
    (void)in_sizes; (void)n_in; (void)out_size;
    const float* hV    = (const float*)d_in[0];
    const float* hE    = (const float*)d_in[1];
    const float* maskV = (const float*)d_in[2];
    const int*   Eidx  = (const int*)d_in[3];
    const float* mA    = (const float*)d_in[4];
    const float* W1w = (const float*)d_in[5],  *W1b = (const float*)d_in[6];
    const float* W2w = (const float*)d_in[7],  *W2b = (const float*)d_in[8];
    const float* W3w = (const float*)d_in[9],  *W3b = (const float*)d_in[10];
    const float* W11w = (const float*)d_in[11], *W11b = (const float*)d_in[12];
    const float* W12w = (const float*)d_in[13], *W12b = (const float*)d_in[14];
    const float* W13w = (const float*)d_in[15], *W13b = (const float*)d_in[16];
    const float* Winw = (const float*)d_in[17], *Winb = (const float*)d_in[18];
    const float* Woutw = (const float*)d_in[19], *Woutb = (const float*)d_in[20];
    const float* ln1g = (const float*)d_in[21], *ln1b = (const float*)d_in[22];
    const float* ln2g = (const float*)d_in[23], *ln2b = (const float*)d_in[24];
    const float* ln3g = (const float*)d_in[25], *ln3b = (const float*)d_in[26];

    float* outV = (float*)d_out;
    float* outE = outV + VOUT;

    cudaFuncSetAttribute(k_pgemm,  cudaFuncAttributeMaxDynamicSharedMemorySize, SMPG);
    cudaFuncSetAttribute(k_stage1, cudaFuncAttributeMaxDynamicSharedMemorySize, SM13);
    cudaFuncSetAttribute(k_stage2, cudaFuncAttributeMaxDynamicSharedMemorySize, SM2);
    cudaFuncSetAttribute(k_stage3, cudaFuncAttributeMaxDynamicSharedMemorySize, SM13);

    k_packW<<<(WPTOT + 255) / 256, 256>>>(W1w, W2w, W3w, W11w, W12w, W13w);
    k_packRow<<<49152, 256>>>(0, (const float4*)hE, (long)ETOT * 32);
    k_packRow<<<1024, 256>>>(1, (const float4*)hV, (long)BN * 32);
    k_pgemm<<<BN / PG_ROWS, 256, SMPG>>>(0);
    k_stage1<<<BN / 2, 256, SM13>>>(hV, mA, W1b, W2b, W3b, ln1g, ln1b);
    k_stage2<<<BN / 32, 256, SM2>>>(maskV, Winw, Winb, Woutw, Woutb,
                                    ln2g, ln2b, outV);
    k_packRow<<<1024, 256>>>(2, (const float4*)outV, (long)BN * 32);
    k_pgemm<<<BN / PG_ROWS, 256, SMPG>>>(1);
    k_stage3<<<BN / 2, 256, SM13>>>(hE, Eidx, W11b, W12b, W13b,
                                    ln3g, ln3b, outE);
}